// round 10
// baseline (speedup 1.0000x reference)
#include <cuda_runtime.h>
#include <cuda_fp16.h>
#include <cstdint>

#define DIMD  1024
#define NH    16
#define DH    64
#define BATCH 4
#define SEQ   2048
#define MTOT  (BATCH*SEQ)   // 8192

// Scratch (allocation-free rule: __device__ globals)
__device__ __align__(16) __half g_QH[BATCH*NH*SEQ*DH];   // [B,H,S,Dh]
__device__ __align__(16) __half g_KH[BATCH*NH*SEQ*DH];
__device__ __align__(16) __half g_VH[BATCH*NH*SEQ*DH];
__device__ __align__(16) __half g_AH[MTOT*DIMD];         // attn out, [B,S,D]
__device__ __align__(16) uint32_t g_WQP[(DIMD/2)*3*DIMD]; // w_qkv packed k-pairs
__device__ __align__(16) uint32_t g_WPP[(DIMD/2)*DIMD];   // w_proj packed

__device__ __forceinline__ unsigned h2u(__half2 h) {
    return *reinterpret_cast<unsigned*>(&h);
}

__device__ __forceinline__ void mma_f16(
    float& c0, float& c1, float& c2, float& c3,
    unsigned a0, unsigned a1, unsigned a2, unsigned a3,
    unsigned b0, unsigned b1)
{
    asm volatile(
        "mma.sync.aligned.m16n8k16.row.col.f32.f16.f16.f32 "
        "{%0,%1,%2,%3}, {%4,%5,%6,%7}, {%8,%9}, {%0,%1,%2,%3};"
        : "+f"(c0), "+f"(c1), "+f"(c2), "+f"(c3)
        : "r"(a0), "r"(a1), "r"(a2), "r"(a3), "r"(b0), "r"(b1));
}

// ---------------------------------------------------------------------------
// One-time prep: w_qkv / w_proj -> k-pairwise packed half2 (x fused into GEMM)
// ---------------------------------------------------------------------------
#define NWQ ((DIMD/2)*(3*DIMD/4))    // 512*768
#define NWP ((DIMD/2)*(DIMD/4))      // 512*256

__global__ __launch_bounds__(256)
void prep(const float* __restrict__ wq, const float* __restrict__ wp)
{
    const int stride = gridDim.x * blockDim.x;
    for (int i = blockIdx.x*blockDim.x + threadIdx.x; i < NWQ; i += stride) {
        const int k2 = i / 768, n4 = i % 768;
        const float4 a = *(const float4*)(wq + (long)(2*k2  )*3072 + n4*4);
        const float4 b = *(const float4*)(wq + (long)(2*k2+1)*3072 + n4*4);
        uint4 o;
        o.x = h2u(__floats2half2_rn(a.x, b.x));
        o.y = h2u(__floats2half2_rn(a.y, b.y));
        o.z = h2u(__floats2half2_rn(a.z, b.z));
        o.w = h2u(__floats2half2_rn(a.w, b.w));
        ((uint4*)g_WQP)[i] = o;
    }
    for (int i = blockIdx.x*blockDim.x + threadIdx.x; i < NWP; i += stride) {
        const int k2 = i / 256, n4 = i % 256;
        const float4 a = *(const float4*)(wp + (long)(2*k2  )*1024 + n4*4);
        const float4 b = *(const float4*)(wp + (long)(2*k2+1)*1024 + n4*4);
        uint4 o;
        o.x = h2u(__floats2half2_rn(a.x, b.x));
        o.y = h2u(__floats2half2_rn(a.y, b.y));
        o.z = h2u(__floats2half2_rn(a.z, b.z));
        o.w = h2u(__floats2half2_rn(a.w, b.w));
        ((uint4*)g_WPP)[i] = o;
    }
}

// ---------------------------------------------------------------------------
// FP16 GEMM, DOUBLE-BUFFERED: block 128x128, 8 warps (4Mx2N), warp 32x64,
// BK=32 halves (16 k-pairs), register-staged prefetch, ONE barrier per chunk.
// MODE 0: A = x (fp32, converted in-register), B=g_WQP (N=3072) -> Q/K/V fp16
// MODE 1: A = g_AH (fp16),                     B=g_WPP (N=1024) -> out fp32
// ---------------------------------------------------------------------------
#define GA_ST 20
#define GB_ST 136
#define GA_STAGE (128*GA_ST)   // 2560 words
#define GB_STAGE (16*GB_ST)    // 2176 words

template<int MODE>
__global__ __launch_bounds__(256, 2)
void gemm_f16(const float* __restrict__ Ax, const float* __restrict__ bias,
              float* __restrict__ out, int N)
{
    __shared__ uint32_t As2[2][GA_STAGE];
    __shared__ uint32_t Bs2[2][GB_STAGE];

    const int tid  = threadIdx.x;
    const int lane = tid & 31;
    const int warp = tid >> 5;
    const int warp_m = warp & 3;
    const int warp_n = warp >> 2;
    const int qr = lane >> 2;
    const int qc = lane & 3;

    const int rowStart = blockIdx.y * 128;
    const int colStart = blockIdx.x * 128;
    const uint32_t* Bp = (MODE == 0) ? g_WQP : g_WPP;

    float acc[2][8][4];
    #pragma unroll
    for (int i = 0; i < 2; i++)
        #pragma unroll
        for (int j = 0; j < 8; j++)
            #pragma unroll
            for (int c = 0; c < 4; c++) acc[i][j][c] = 0.f;

    // staging registers
    float4 axf[4];    // MODE 0: fp32 A (4 float4 = 16 floats)
    uint4  axh[2];    // MODE 1: fp16 A
    uint4  bvs[2];

    auto ldg_chunk = [&](int k0) {
        if (MODE == 0) {
            #pragma unroll
            for (int i = 0; i < 4; i++) {
                const int q = tid + i*256;          // 1024 float4 slots
                axf[i] = *(const float4*)(Ax + (long)(rowStart + (q>>3))*DIMD + k0 + ((q&7)<<2));
            }
        } else {
            #pragma unroll
            for (int i = 0; i < 2; i++) {
                const int q = tid + i*256;          // 512 uint4 slots
                axh[i] = *(const uint4*)(g_AH + (long)(rowStart + (q>>2))*DIMD + k0 + ((q&3)<<3));
            }
        }
        #pragma unroll
        for (int i = 0; i < 2; i++) {
            const int q = tid + i*256;              // 512 uint4 slots
            bvs[i] = *(const uint4*)(Bp + (long)((k0>>1) + (q>>5))*N + colStart + ((q&31)<<2));
        }
    };
    auto sts_chunk = [&](int s) {
        if (MODE == 0) {
            #pragma unroll
            for (int i = 0; i < 4; i++) {
                const int q = tid + i*256;
                uint2 p;
                p.x = h2u(__floats2half2_rn(axf[i].x, axf[i].y));
                p.y = h2u(__floats2half2_rn(axf[i].z, axf[i].w));
                *(uint2*)(&As2[s][(q>>3)*GA_ST + ((q&7)<<1)]) = p;
            }
        } else {
            #pragma unroll
            for (int i = 0; i < 2; i++) {
                const int q = tid + i*256;
                *(uint4*)(&As2[s][(q>>2)*GA_ST + ((q&3)<<2)]) = axh[i];
            }
        }
        #pragma unroll
        for (int i = 0; i < 2; i++) {
            const int q = tid + i*256;
            *(uint4*)(&Bs2[s][(q>>5)*GB_ST + ((q&31)<<2)]) = bvs[i];
        }
    };

    ldg_chunk(0);
    sts_chunk(0);
    __syncthreads();

    const int NITER = DIMD / 32;   // 32
    for (int it = 0; it < NITER; it++) {
        const int cur = it & 1;
        const bool more = (it + 1) < NITER;
        if (more) ldg_chunk((it + 1) << 5);

        const uint32_t* as = As2[cur];
        const uint32_t* bs = Bs2[cur];
        #pragma unroll
        for (int ks = 0; ks < 2; ks++) {
            const int kb2 = ks * 8;
            unsigned a[2][4], b[8][2];
            #pragma unroll
            for (int ma = 0; ma < 2; ma++) {
                const int r = warp_m*32 + ma*16 + qr;
                a[ma][0] = as[(r    )*GA_ST + kb2 + qc    ];
                a[ma][1] = as[(r + 8)*GA_ST + kb2 + qc    ];
                a[ma][2] = as[(r    )*GA_ST + kb2 + qc + 4];
                a[ma][3] = as[(r + 8)*GA_ST + kb2 + qc + 4];
            }
            #pragma unroll
            for (int nb = 0; nb < 8; nb++) {
                const int cc = warp_n*64 + nb*8 + qr;
                b[nb][0] = bs[(kb2 + qc    )*GB_ST + cc];
                b[nb][1] = bs[(kb2 + qc + 4)*GB_ST + cc];
            }
            #pragma unroll
            for (int ma = 0; ma < 2; ma++)
                #pragma unroll
                for (int nb = 0; nb < 8; nb++)
                    mma_f16(acc[ma][nb][0], acc[ma][nb][1],
                            acc[ma][nb][2], acc[ma][nb][3],
                            a[ma][0], a[ma][1], a[ma][2], a[ma][3],
                            b[nb][0], b[nb][1]);
        }

        if (more) {
            sts_chunk(cur ^ 1);
            __syncthreads();
        }
    }

    #pragma unroll
    for (int ma = 0; ma < 2; ma++) {
        const int row0 = rowStart + warp_m*32 + ma*16 + qr;
        #pragma unroll
        for (int nb = 0; nb < 8; nb++) {
            const int col = colStart + warp_n*64 + nb*8 + qc*2;
            const float b0 = bias[col], b1 = bias[col + 1];
            const float v00 = acc[ma][nb][0] + b0, v01 = acc[ma][nb][1] + b1;
            const float v10 = acc[ma][nb][2] + b0, v11 = acc[ma][nb][3] + b1;
            if (MODE == 0) {
                const int part = col >> 10;
                const int dcol = col & 1023;
                const int head = dcol >> 6;
                const int dh   = dcol & 63;
                __half* dst = (part == 0) ? g_QH : (part == 1) ? g_KH : g_VH;
                {
                    const int bb = row0 >> 11, s = row0 & 2047;
                    *(__half2*)(dst + (((bb*NH + head)*SEQ + s) << 6) + dh) =
                        __floats2half2_rn(v00, v01);
                }
                {
                    const int row1 = row0 + 8;
                    const int bb = row1 >> 11, s = row1 & 2047;
                    *(__half2*)(dst + (((bb*NH + head)*SEQ + s) << 6) + dh) =
                        __floats2half2_rn(v10, v11);
                }
            } else {
                *(float2*)(out + (long)row0*N + col) = make_float2(v00, v01);
                *(float2*)(out + (long)(row0 + 8)*N + col) = make_float2(v10, v11);
            }
        }
    }
}

// ---------------------------------------------------------------------------
// FP16 flash attention (unchanged from round 9).
// ---------------------------------------------------------------------------
#define AQ_ST 36
#define KV_STAGE (64*AQ_ST)                       // 2304 words
#define ATTN_SMEM_WORDS (128*AQ_ST + 4*KV_STAGE)  // 13824
#define ATTN_SMEM_BYTES (ATTN_SMEM_WORDS*4)       // 55296

__global__ __launch_bounds__(256, 2)
void attn_f16()
{
    extern __shared__ uint32_t smw[];
    uint32_t* Qs2 = smw;                         // [128][36]
    uint32_t* KsB = smw + 128*AQ_ST;             // [2][64][36]
    uint32_t* VtB = smw + 128*AQ_ST + 2*KV_STAGE;// [2][64][36]  (V^T, key-pairs)

    const int tid  = threadIdx.x;
    const int lane = tid & 31;
    const int warp = tid >> 5;
    const int qr = lane >> 2;
    const int qc = lane & 3;

    const int qt = (int)(gridDim.x - 1) - (int)blockIdx.x;   // heavy tiles first
    const int h = blockIdx.y, b = blockIdx.z;
    const int q0 = qt << 7;

    const long hb = (long)(b*NH + h) * SEQ * DH;
    const __half* Qg = g_QH + hb;
    const __half* Kg = g_KH + hb;
    const __half* Vg = g_VH + hb;

    const __half2 hscale = __float2half2_rn(0.125f);
    #pragma unroll
    for (int i = 0; i < 4; i++) {
        const int q = tid + i*256;
        const int r = q >> 3, w = q & 7;
        uint4 t = *(const uint4*)(Qg + (q0 + r)*DH + w*8);
        __half2* hp = (__half2*)&t;
        hp[0] = __hmul2(hp[0], hscale); hp[1] = __hmul2(hp[1], hscale);
        hp[2] = __hmul2(hp[2], hscale); hp[3] = __hmul2(hp[3], hscale);
        *(uint4*)(&Qs2[r*AQ_ST + w*4]) = t;
    }

    const int vk2  = tid & 31;
    const int vdb  = (tid >> 5) << 3;

    {
        #pragma unroll
        for (int i = 0; i < 2; i++) {
            const int q = tid + i*256;
            const int r = q >> 3, w = q & 7;
            *(uint4*)(&KsB[r*AQ_ST + w*4]) = *(const uint4*)(Kg + r*DH + w*8);
        }
        uint4 lo = *(const uint4*)(Vg + (2*vk2    )*DH + vdb);
        uint4 hi = *(const uint4*)(Vg + (2*vk2 + 1)*DH + vdb);
        const __half* la = (const __half*)&lo;
        const __half* hb2 = (const __half*)&hi;
        #pragma unroll
        for (int j = 0; j < 8; j++)
            VtB[(vdb + j)*AQ_ST + vk2] = h2u(__halves2half2(la[j], hb2[j]));
    }
    __syncthreads();

    float m0 = -1e30f, m1 = -1e30f, l0 = 0.f, l1 = 0.f;
    float o[8][4];
    #pragma unroll
    for (int nb = 0; nb < 8; nb++)
        #pragma unroll
        for (int c = 0; c < 4; c++) o[nb][c] = 0.f;

    const int rowA = warp*16 + qr;
    const int ktiles = 2*qt + 2;

    for (int kt = 0; kt < ktiles; kt++) {
        const int cur = kt & 1;
        const bool more = (kt + 1) < ktiles;
        const uint32_t* Ks = KsB + cur*KV_STAGE;
        const uint32_t* Vt = VtB + cur*KV_STAGE;

        uint4 kreg[2], vlo, vhi;
        if (more) {
            const int k1 = (kt + 1) << 6;
            #pragma unroll
            for (int i = 0; i < 2; i++) {
                const int q = tid + i*256;
                kreg[i] = *(const uint4*)(Kg + (k1 + (q>>3))*DH + (q&7)*8);
            }
            vlo = *(const uint4*)(Vg + (k1 + 2*vk2    )*DH + vdb);
            vhi = *(const uint4*)(Vg + (k1 + 2*vk2 + 1)*DH + vdb);
        }

        float sv[8][4];
        #pragma unroll
        for (int nb = 0; nb < 8; nb++)
            #pragma unroll
            for (int c = 0; c < 4; c++) sv[nb][c] = 0.f;

        #pragma unroll
        for (int ks = 0; ks < 4; ks++) {
            const int kb2 = ks*8;
            const unsigned a0 = Qs2[(rowA    )*AQ_ST + kb2 + qc    ];
            const unsigned a1 = Qs2[(rowA + 8)*AQ_ST + kb2 + qc    ];
            const unsigned a2 = Qs2[(rowA    )*AQ_ST + kb2 + qc + 4];
            const unsigned a3 = Qs2[(rowA + 8)*AQ_ST + kb2 + qc + 4];
            #pragma unroll
            for (int nb = 0; nb < 8; nb++) {
                const unsigned b0 = Ks[(nb*8+qr)*AQ_ST + kb2 + qc    ];
                const unsigned b1 = Ks[(nb*8+qr)*AQ_ST + kb2 + qc + 4];
                mma_f16(sv[nb][0], sv[nb][1], sv[nb][2], sv[nb][3],
                        a0, a1, a2, a3, b0, b1);
            }
        }

        if (kt >= 2*qt) {
            const int k0 = kt << 6;
            const int qg0 = q0 + rowA;
            #pragma unroll
            for (int nb = 0; nb < 8; nb++) {
                const int kg = k0 + nb*8 + 2*qc;
                if (kg     > qg0    ) sv[nb][0] = -1e30f;
                if (kg + 1 > qg0    ) sv[nb][1] = -1e30f;
                if (kg     > qg0 + 8) sv[nb][2] = -1e30f;
                if (kg + 1 > qg0 + 8) sv[nb][3] = -1e30f;
            }
        }

        float mx0 = -1e30f, mx1 = -1e30f;
        #pragma unroll
        for (int nb = 0; nb < 8; nb++) {
            mx0 = fmaxf(mx0, fmaxf(sv[nb][0], sv[nb][1]));
            mx1 = fmaxf(mx1, fmaxf(sv[nb][2], sv[nb][3]));
        }
        mx0 = fmaxf(mx0, __shfl_xor_sync(0xffffffffu, mx0, 1));
        mx0 = fmaxf(mx0, __shfl_xor_sync(0xffffffffu, mx0, 2));
        mx1 = fmaxf(mx1, __shfl_xor_sync(0xffffffffu, mx1, 1));
        mx1 = fmaxf(mx1, __shfl_xor_sync(0xffffffffu, mx1, 2));

        const float m0n = fmaxf(m0, mx0);
        const float m1n = fmaxf(m1, mx1);
        const float al0 = __expf(m0 - m0n);
        const float al1 = __expf(m1 - m1n);
        m0 = m0n; m1 = m1n;

        float ps0 = 0.f, ps1 = 0.f;
        #pragma unroll
        for (int nb = 0; nb < 8; nb++) {
            sv[nb][0] = __expf(sv[nb][0] - m0n);
            sv[nb][1] = __expf(sv[nb][1] - m0n);
            sv[nb][2] = __expf(sv[nb][2] - m1n);
            sv[nb][3] = __expf(sv[nb][3] - m1n);
            ps0 += sv[nb][0] + sv[nb][1];
            ps1 += sv[nb][2] + sv[nb][3];
        }
        ps0 += __shfl_xor_sync(0xffffffffu, ps0, 1);
        ps0 += __shfl_xor_sync(0xffffffffu, ps0, 2);
        ps1 += __shfl_xor_sync(0xffffffffu, ps1, 1);
        ps1 += __shfl_xor_sync(0xffffffffu, ps1, 2);
        l0 = l0*al0 + ps0;
        l1 = l1*al1 + ps1;
        #pragma unroll
        for (int nb = 0; nb < 8; nb++) {
            o[nb][0] *= al0; o[nb][1] *= al0;
            o[nb][2] *= al1; o[nb][3] *= al1;
        }

        #pragma unroll
        for (int ks = 0; ks < 4; ks++) {
            const unsigned a0 = h2u(__floats2half2_rn(sv[2*ks  ][0], sv[2*ks  ][1]));
            const unsigned a1 = h2u(__floats2half2_rn(sv[2*ks  ][2], sv[2*ks  ][3]));
            const unsigned a2 = h2u(__floats2half2_rn(sv[2*ks+1][0], sv[2*ks+1][1]));
            const unsigned a3 = h2u(__floats2half2_rn(sv[2*ks+1][2], sv[2*ks+1][3]));
            #pragma unroll
            for (int nb = 0; nb < 8; nb++) {
                const unsigned b0 = Vt[(nb*8+qr)*AQ_ST + ks*8 + qc    ];
                const unsigned b1 = Vt[(nb*8+qr)*AQ_ST + ks*8 + qc + 4];
                mma_f16(o[nb][0], o[nb][1], o[nb][2], o[nb][3],
                        a0, a1, a2, a3, b0, b1);
            }
        }

        if (more) {
            const int nxt = cur ^ 1;
            uint32_t* KsD = KsB + nxt*KV_STAGE;
            uint32_t* VtD = VtB + nxt*KV_STAGE;
            #pragma unroll
            for (int i = 0; i < 2; i++) {
                const int q = tid + i*256;
                *(uint4*)(&KsD[(q>>3)*AQ_ST + (q&7)*4]) = kreg[i];
            }
            const __half* la = (const __half*)&vlo;
            const __half* hb2 = (const __half*)&vhi;
            #pragma unroll
            for (int j = 0; j < 8; j++)
                VtD[(vdb + j)*AQ_ST + vk2] = h2u(__halves2half2(la[j], hb2[j]));
            __syncthreads();
        }
    }

    const float inv0 = 1.0f / l0;
    const float inv1 = 1.0f / l1;
    const long r0 = (long)(b*SEQ + q0 + rowA);
    #pragma unroll
    for (int nb = 0; nb < 8; nb++) {
        const int col = h*DH + nb*8 + 2*qc;
        *(__half2*)(g_AH + r0*DIMD + col) =
            __floats2half2_rn(o[nb][0]*inv0, o[nb][1]*inv0);
        *(__half2*)(g_AH + (r0 + 8)*DIMD + col) =
            __floats2half2_rn(o[nb][2]*inv1, o[nb][3]*inv1);
    }
}

// ---------------------------------------------------------------------------
extern "C" void kernel_launch(void* const* d_in, const int* in_sizes, int n_in,
                              void* d_out, int out_size)
{
    const float* x      = (const float*)d_in[0];
    const float* w_qkv  = (const float*)d_in[1];
    const float* b_qkv  = (const float*)d_in[2];
    const float* w_proj = (const float*)d_in[3];
    const float* b_proj = (const float*)d_in[4];
    float* out = (float*)d_out;

    cudaFuncSetAttribute(attn_f16,
        cudaFuncAttributeMaxDynamicSharedMemorySize, ATTN_SMEM_BYTES);

    prep<<<512, 256>>>(w_qkv, w_proj);
    gemm_f16<0><<<dim3(3*DIMD/128, MTOT/128), 256>>>(x, b_qkv, nullptr, 3*DIMD);
    attn_f16<<<dim3(SEQ/128, NH, BATCH), 256, ATTN_SMEM_BYTES>>>();
    gemm_f16<1><<<dim3(DIMD/128, MTOT/128), 256>>>(nullptr, b_proj, out, DIMD);
}

// round 11
// speedup vs baseline: 1.1128x; 1.1128x over previous
#include <cuda_runtime.h>
#include <cuda_fp16.h>
#include <cstdint>

#define DIMD  1024
#define NH    16
#define DH    64
#define BATCH 4
#define SEQ   2048
#define MTOT  (BATCH*SEQ)   // 8192

// Scratch (allocation-free rule: __device__ globals)
__device__ __align__(16) __half g_QH[BATCH*NH*SEQ*DH];   // [B,H,S,Dh]
__device__ __align__(16) __half g_KH[BATCH*NH*SEQ*DH];
__device__ __align__(16) __half g_VH[BATCH*NH*SEQ*DH];
__device__ __align__(16) __half g_AH[MTOT*DIMD];         // attn out, [B,S,D]
__device__ __align__(16) __half g_XH[MTOT*DIMD];         // x as fp16
__device__ __align__(16) uint32_t g_WQP[(DIMD/2)*3*DIMD]; // w_qkv packed k-pairs
__device__ __align__(16) uint32_t g_WPP[(DIMD/2)*DIMD];   // w_proj packed

__device__ __forceinline__ unsigned h2u(__half2 h) {
    return *reinterpret_cast<unsigned*>(&h);
}

__device__ __forceinline__ void mma_f16(
    float& c0, float& c1, float& c2, float& c3,
    unsigned a0, unsigned a1, unsigned a2, unsigned a3,
    unsigned b0, unsigned b1)
{
    asm volatile(
        "mma.sync.aligned.m16n8k16.row.col.f32.f16.f16.f32 "
        "{%0,%1,%2,%3}, {%4,%5,%6,%7}, {%8,%9}, {%0,%1,%2,%3};"
        : "+f"(c0), "+f"(c1), "+f"(c2), "+f"(c3)
        : "r"(a0), "r"(a1), "r"(a2), "r"(a3), "r"(b0), "r"(b1));
}

__device__ __forceinline__ void cpa16(void* dst, const void* src) {
    unsigned s = (unsigned)__cvta_generic_to_shared(dst);
    asm volatile("cp.async.cg.shared.global [%0], [%1], 16;" :: "r"(s), "l"(src));
}
__device__ __forceinline__ void cpa_commit() {
    asm volatile("cp.async.commit_group;");
}
template<int N>
__device__ __forceinline__ void cpa_wait() {
    asm volatile("cp.async.wait_group %0;" :: "n"(N));
}

// ---------------------------------------------------------------------------
// One-time prep: x -> fp16; w_qkv / w_proj -> k-pairwise packed half2
// ---------------------------------------------------------------------------
#define NX4 (MTOT*DIMD/4)            // 2097152
#define NWQ ((DIMD/2)*(3*DIMD/4))    // 512*768
#define NWP ((DIMD/2)*(DIMD/4))      // 512*256

__global__ __launch_bounds__(256)
void prep(const float* __restrict__ x, const float* __restrict__ wq,
          const float* __restrict__ wp)
{
    const int stride = gridDim.x * blockDim.x;
    for (int i = blockIdx.x*blockDim.x + threadIdx.x; i < NX4; i += stride) {
        float4 t = ((const float4*)x)[i];
        uint2 o;
        o.x = h2u(__floats2half2_rn(t.x, t.y));
        o.y = h2u(__floats2half2_rn(t.z, t.w));
        ((uint2*)g_XH)[i] = o;
    }
    for (int i = blockIdx.x*blockDim.x + threadIdx.x; i < NWQ; i += stride) {
        const int k2 = i / 768, n4 = i % 768;
        const float4 a = *(const float4*)(wq + (long)(2*k2  )*3072 + n4*4);
        const float4 b = *(const float4*)(wq + (long)(2*k2+1)*3072 + n4*4);
        uint4 o;
        o.x = h2u(__floats2half2_rn(a.x, b.x));
        o.y = h2u(__floats2half2_rn(a.y, b.y));
        o.z = h2u(__floats2half2_rn(a.z, b.z));
        o.w = h2u(__floats2half2_rn(a.w, b.w));
        ((uint4*)g_WQP)[i] = o;
    }
    for (int i = blockIdx.x*blockDim.x + threadIdx.x; i < NWP; i += stride) {
        const int k2 = i / 256, n4 = i % 256;
        const float4 a = *(const float4*)(wp + (long)(2*k2  )*1024 + n4*4);
        const float4 b = *(const float4*)(wp + (long)(2*k2+1)*1024 + n4*4);
        uint4 o;
        o.x = h2u(__floats2half2_rn(a.x, b.x));
        o.y = h2u(__floats2half2_rn(a.y, b.y));
        o.z = h2u(__floats2half2_rn(a.z, b.z));
        o.w = h2u(__floats2half2_rn(a.w, b.w));
        ((uint4*)g_WPP)[i] = o;
    }
}

// ---------------------------------------------------------------------------
// FP16 GEMM, 4-stage cp.async pipeline: block 128x128, 8 warps (4Mx2N),
// warp 32x64, BK=32 halves. Issue stage it+3 AFTER computing stage it
// (buffer consumed at it-1, fenced by this iteration's top barrier) ->
// ONE barrier per chunk, race-free, no staging registers.
// MODE 0: A=g_XH, B=g_WQP (N=3072) -> Q/K/V fp16
// MODE 1: A=g_AH, B=g_WPP (N=1024) -> out fp32
// ---------------------------------------------------------------------------
#define GA_ST 20
#define GB_ST 136
#define GA_STAGE (128*GA_ST)   // 2560 words
#define GB_STAGE (16*GB_ST)    // 2176 words
#define STG 4
#define GEMM_SMEM_WORDS (STG*(GA_STAGE+GB_STAGE))   // 18944
#define GEMM_SMEM_BYTES (GEMM_SMEM_WORDS*4)         // 75776

template<int MODE>
__global__ __launch_bounds__(256, 2)
void gemm_f16(const float* __restrict__ bias, float* __restrict__ out, int N)
{
    extern __shared__ uint32_t smw[];
    uint32_t* As2 = smw;                    // [STG][128][20]
    uint32_t* Bs2 = smw + STG*GA_STAGE;     // [STG][16][136]

    const int tid  = threadIdx.x;
    const int lane = tid & 31;
    const int warp = tid >> 5;
    const int warp_m = warp & 3;
    const int warp_n = warp >> 2;
    const int qr = lane >> 2;
    const int qc = lane & 3;

    const int rowStart = blockIdx.y * 128;
    const int colStart = blockIdx.x * 128;
    const __half* Ap = (MODE == 0) ? g_XH : g_AH;
    const uint32_t* Bp = (MODE == 0) ? g_WQP : g_WPP;

    float acc[2][8][4];
    #pragma unroll
    for (int i = 0; i < 2; i++)
        #pragma unroll
        for (int j = 0; j < 8; j++)
            #pragma unroll
            for (int c = 0; c < 4; c++) acc[i][j][c] = 0.f;

    auto load_stage = [&](int s, int k0) {
        uint32_t* as = As2 + s*GA_STAGE;
        uint32_t* bs = Bs2 + s*GB_STAGE;
        #pragma unroll
        for (int i = 0; i < 2; i++) {
            const int q = tid + i*256;      // A: 128 rows x 4 slots of 8 halves
            cpa16(as + (q>>2)*GA_ST + ((q&3)<<2),
                  Ap + (long)(rowStart + (q>>2))*DIMD + k0 + ((q&3)<<3));
        }
        #pragma unroll
        for (int i = 0; i < 2; i++) {
            const int q = tid + i*256;      // B: 16 k2-rows x 32 word-quads
            cpa16(bs + (q>>5)*GB_ST + ((q&31)<<2),
                  Bp + (long)((k0>>1) + (q>>5))*N + colStart + ((q&31)<<2));
        }
    };

    // prologue: stages 0..2 in flight
    #pragma unroll
    for (int s = 0; s < STG-1; s++) { load_stage(s, s*32); cpa_commit(); }

    const int NITER = DIMD / 32;   // 32
    for (int it = 0; it < NITER; it++) {
        cpa_wait<STG-2>();         // stage `it` complete (see group arithmetic)
        __syncthreads();           // visible to all warps; prior stage consumed

        const int cur = it & (STG-1);
        const uint32_t* as = As2 + cur*GA_STAGE;
        const uint32_t* bs = Bs2 + cur*GB_STAGE;
        #pragma unroll
        for (int ks = 0; ks < 2; ks++) {
            const int kb2 = ks * 8;
            unsigned a[2][4], b[8][2];
            #pragma unroll
            for (int ma = 0; ma < 2; ma++) {
                const int r = warp_m*32 + ma*16 + qr;
                a[ma][0] = as[(r    )*GA_ST + kb2 + qc    ];
                a[ma][1] = as[(r + 8)*GA_ST + kb2 + qc    ];
                a[ma][2] = as[(r    )*GA_ST + kb2 + qc + 4];
                a[ma][3] = as[(r + 8)*GA_ST + kb2 + qc + 4];
            }
            #pragma unroll
            for (int nb = 0; nb < 8; nb++) {
                const int cc = warp_n*64 + nb*8 + qr;
                b[nb][0] = bs[(kb2 + qc    )*GB_ST + cc];
                b[nb][1] = bs[(kb2 + qc + 4)*GB_ST + cc];
            }
            #pragma unroll
            for (int ma = 0; ma < 2; ma++)
                #pragma unroll
                for (int nb = 0; nb < 8; nb++)
                    mma_f16(acc[ma][nb][0], acc[ma][nb][1],
                            acc[ma][nb][2], acc[ma][nb][3],
                            a[ma][0], a[ma][1], a[ma][2], a[ma][3],
                            b[nb][0], b[nb][1]);
        }

        // issue stage it+3 into the buffer consumed at iteration it-1
        const int nk = it + STG - 1;
        if (nk < NITER) load_stage(nk & (STG-1), nk*32);
        cpa_commit();   // unconditional: keeps wait_group arithmetic uniform
    }

    #pragma unroll
    for (int ma = 0; ma < 2; ma++) {
        const int row0 = rowStart + warp_m*32 + ma*16 + qr;
        #pragma unroll
        for (int nb = 0; nb < 8; nb++) {
            const int col = colStart + warp_n*64 + nb*8 + qc*2;
            const float b0 = bias[col], b1 = bias[col + 1];
            const float v00 = acc[ma][nb][0] + b0, v01 = acc[ma][nb][1] + b1;
            const float v10 = acc[ma][nb][2] + b0, v11 = acc[ma][nb][3] + b1;
            if (MODE == 0) {
                const int part = col >> 10;
                const int dcol = col & 1023;
                const int head = dcol >> 6;
                const int dh   = dcol & 63;
                __half* dst = (part == 0) ? g_QH : (part == 1) ? g_KH : g_VH;
                {
                    const int bb = row0 >> 11, s = row0 & 2047;
                    *(__half2*)(dst + (((bb*NH + head)*SEQ + s) << 6) + dh) =
                        __floats2half2_rn(v00, v01);
                }
                {
                    const int row1 = row0 + 8;
                    const int bb = row1 >> 11, s = row1 & 2047;
                    *(__half2*)(dst + (((bb*NH + head)*SEQ + s) << 6) + dh) =
                        __floats2half2_rn(v10, v11);
                }
            } else {
                *(float2*)(out + (long)row0*N + col) = make_float2(v00, v01);
                *(float2*)(out + (long)(row0 + 8)*N + col) = make_float2(v10, v11);
            }
        }
    }
}

// ---------------------------------------------------------------------------
// FP16 flash attention (unchanged — the 494us configuration).
// ---------------------------------------------------------------------------
#define AQ_ST 36
#define KV_STAGE (64*AQ_ST)                       // 2304 words
#define ATTN_SMEM_WORDS (128*AQ_ST + 4*KV_STAGE)  // 13824
#define ATTN_SMEM_BYTES (ATTN_SMEM_WORDS*4)       // 55296

__global__ __launch_bounds__(256, 2)
void attn_f16()
{
    extern __shared__ uint32_t smw[];
    uint32_t* Qs2 = smw;                         // [128][36]
    uint32_t* KsB = smw + 128*AQ_ST;             // [2][64][36]
    uint32_t* VtB = smw + 128*AQ_ST + 2*KV_STAGE;// [2][64][36]  (V^T, key-pairs)

    const int tid  = threadIdx.x;
    const int lane = tid & 31;
    const int warp = tid >> 5;
    const int qr = lane >> 2;
    const int qc = lane & 3;

    const int qt = (int)(gridDim.x - 1) - (int)blockIdx.x;   // heavy tiles first
    const int h = blockIdx.y, b = blockIdx.z;
    const int q0 = qt << 7;

    const long hb = (long)(b*NH + h) * SEQ * DH;
    const __half* Qg = g_QH + hb;
    const __half* Kg = g_KH + hb;
    const __half* Vg = g_VH + hb;

    const __half2 hscale = __float2half2_rn(0.125f);
    #pragma unroll
    for (int i = 0; i < 4; i++) {
        const int q = tid + i*256;
        const int r = q >> 3, w = q & 7;
        uint4 t = *(const uint4*)(Qg + (q0 + r)*DH + w*8);
        __half2* hp = (__half2*)&t;
        hp[0] = __hmul2(hp[0], hscale); hp[1] = __hmul2(hp[1], hscale);
        hp[2] = __hmul2(hp[2], hscale); hp[3] = __hmul2(hp[3], hscale);
        *(uint4*)(&Qs2[r*AQ_ST + w*4]) = t;
    }

    const int vk2  = tid & 31;
    const int vdb  = (tid >> 5) << 3;

    {
        #pragma unroll
        for (int i = 0; i < 2; i++) {
            const int q = tid + i*256;
            const int r = q >> 3, w = q & 7;
            *(uint4*)(&KsB[r*AQ_ST + w*4]) = *(const uint4*)(Kg + r*DH + w*8);
        }
        uint4 lo = *(const uint4*)(Vg + (2*vk2    )*DH + vdb);
        uint4 hi = *(const uint4*)(Vg + (2*vk2 + 1)*DH + vdb);
        const __half* la = (const __half*)&lo;
        const __half* hb2 = (const __half*)&hi;
        #pragma unroll
        for (int j = 0; j < 8; j++)
            VtB[(vdb + j)*AQ_ST + vk2] = h2u(__halves2half2(la[j], hb2[j]));
    }
    __syncthreads();

    float m0 = -1e30f, m1 = -1e30f, l0 = 0.f, l1 = 0.f;
    float o[8][4];
    #pragma unroll
    for (int nb = 0; nb < 8; nb++)
        #pragma unroll
        for (int c = 0; c < 4; c++) o[nb][c] = 0.f;

    const int rowA = warp*16 + qr;
    const int ktiles = 2*qt + 2;

    for (int kt = 0; kt < ktiles; kt++) {
        const int cur = kt & 1;
        const bool more = (kt + 1) < ktiles;
        const uint32_t* Ks = KsB + cur*KV_STAGE;
        const uint32_t* Vt = VtB + cur*KV_STAGE;

        uint4 kreg[2], vlo, vhi;
        if (more) {
            const int k1 = (kt + 1) << 6;
            #pragma unroll
            for (int i = 0; i < 2; i++) {
                const int q = tid + i*256;
                kreg[i] = *(const uint4*)(Kg + (k1 + (q>>3))*DH + (q&7)*8);
            }
            vlo = *(const uint4*)(Vg + (k1 + 2*vk2    )*DH + vdb);
            vhi = *(const uint4*)(Vg + (k1 + 2*vk2 + 1)*DH + vdb);
        }

        float sv[8][4];
        #pragma unroll
        for (int nb = 0; nb < 8; nb++)
            #pragma unroll
            for (int c = 0; c < 4; c++) sv[nb][c] = 0.f;

        #pragma unroll
        for (int ks = 0; ks < 4; ks++) {
            const int kb2 = ks*8;
            const unsigned a0 = Qs2[(rowA    )*AQ_ST + kb2 + qc    ];
            const unsigned a1 = Qs2[(rowA + 8)*AQ_ST + kb2 + qc    ];
            const unsigned a2 = Qs2[(rowA    )*AQ_ST + kb2 + qc + 4];
            const unsigned a3 = Qs2[(rowA + 8)*AQ_ST + kb2 + qc + 4];
            #pragma unroll
            for (int nb = 0; nb < 8; nb++) {
                const unsigned b0 = Ks[(nb*8+qr)*AQ_ST + kb2 + qc    ];
                const unsigned b1 = Ks[(nb*8+qr)*AQ_ST + kb2 + qc + 4];
                mma_f16(sv[nb][0], sv[nb][1], sv[nb][2], sv[nb][3],
                        a0, a1, a2, a3, b0, b1);
            }
        }

        if (kt >= 2*qt) {
            const int k0 = kt << 6;
            const int qg0 = q0 + rowA;
            #pragma unroll
            for (int nb = 0; nb < 8; nb++) {
                const int kg = k0 + nb*8 + 2*qc;
                if (kg     > qg0    ) sv[nb][0] = -1e30f;
                if (kg + 1 > qg0    ) sv[nb][1] = -1e30f;
                if (kg     > qg0 + 8) sv[nb][2] = -1e30f;
                if (kg + 1 > qg0 + 8) sv[nb][3] = -1e30f;
            }
        }

        float mx0 = -1e30f, mx1 = -1e30f;
        #pragma unroll
        for (int nb = 0; nb < 8; nb++) {
            mx0 = fmaxf(mx0, fmaxf(sv[nb][0], sv[nb][1]));
            mx1 = fmaxf(mx1, fmaxf(sv[nb][2], sv[nb][3]));
        }
        mx0 = fmaxf(mx0, __shfl_xor_sync(0xffffffffu, mx0, 1));
        mx0 = fmaxf(mx0, __shfl_xor_sync(0xffffffffu, mx0, 2));
        mx1 = fmaxf(mx1, __shfl_xor_sync(0xffffffffu, mx1, 1));
        mx1 = fmaxf(mx1, __shfl_xor_sync(0xffffffffu, mx1, 2));

        const float m0n = fmaxf(m0, mx0);
        const float m1n = fmaxf(m1, mx1);
        const float al0 = __expf(m0 - m0n);
        const float al1 = __expf(m1 - m1n);
        m0 = m0n; m1 = m1n;

        float ps0 = 0.f, ps1 = 0.f;
        #pragma unroll
        for (int nb = 0; nb < 8; nb++) {
            sv[nb][0] = __expf(sv[nb][0] - m0n);
            sv[nb][1] = __expf(sv[nb][1] - m0n);
            sv[nb][2] = __expf(sv[nb][2] - m1n);
            sv[nb][3] = __expf(sv[nb][3] - m1n);
            ps0 += sv[nb][0] + sv[nb][1];
            ps1 += sv[nb][2] + sv[nb][3];
        }
        ps0 += __shfl_xor_sync(0xffffffffu, ps0, 1);
        ps0 += __shfl_xor_sync(0xffffffffu, ps0, 2);
        ps1 += __shfl_xor_sync(0xffffffffu, ps1, 1);
        ps1 += __shfl_xor_sync(0xffffffffu, ps1, 2);
        l0 = l0*al0 + ps0;
        l1 = l1*al1 + ps1;
        #pragma unroll
        for (int nb = 0; nb < 8; nb++) {
            o[nb][0] *= al0; o[nb][1] *= al0;
            o[nb][2] *= al1; o[nb][3] *= al1;
        }

        #pragma unroll
        for (int ks = 0; ks < 4; ks++) {
            const unsigned a0 = h2u(__floats2half2_rn(sv[2*ks  ][0], sv[2*ks  ][1]));
            const unsigned a1 = h2u(__floats2half2_rn(sv[2*ks  ][2], sv[2*ks  ][3]));
            const unsigned a2 = h2u(__floats2half2_rn(sv[2*ks+1][0], sv[2*ks+1][1]));
            const unsigned a3 = h2u(__floats2half2_rn(sv[2*ks+1][2], sv[2*ks+1][3]));
            #pragma unroll
            for (int nb = 0; nb < 8; nb++) {
                const unsigned b0 = Vt[(nb*8+qr)*AQ_ST + ks*8 + qc    ];
                const unsigned b1 = Vt[(nb*8+qr)*AQ_ST + ks*8 + qc + 4];
                mma_f16(o[nb][0], o[nb][1], o[nb][2], o[nb][3],
                        a0, a1, a2, a3, b0, b1);
            }
        }

        if (more) {
            const int nxt = cur ^ 1;
            uint32_t* KsD = KsB + nxt*KV_STAGE;
            uint32_t* VtD = VtB + nxt*KV_STAGE;
            #pragma unroll
            for (int i = 0; i < 2; i++) {
                const int q = tid + i*256;
                *(uint4*)(&KsD[(q>>3)*AQ_ST + (q&7)*4]) = kreg[i];
            }
            const __half* la = (const __half*)&vlo;
            const __half* hb2 = (const __half*)&vhi;
            #pragma unroll
            for (int j = 0; j < 8; j++)
                VtD[(vdb + j)*AQ_ST + vk2] = h2u(__halves2half2(la[j], hb2[j]));
            __syncthreads();
        }
    }

    const float inv0 = 1.0f / l0;
    const float inv1 = 1.0f / l1;
    const long r0 = (long)(b*SEQ + q0 + rowA);
    #pragma unroll
    for (int nb = 0; nb < 8; nb++) {
        const int col = h*DH + nb*8 + 2*qc;
        *(__half2*)(g_AH + r0*DIMD + col) =
            __floats2half2_rn(o[nb][0]*inv0, o[nb][1]*inv0);
        *(__half2*)(g_AH + (r0 + 8)*DIMD + col) =
            __floats2half2_rn(o[nb][2]*inv1, o[nb][3]*inv1);
    }
}

// ---------------------------------------------------------------------------
extern "C" void kernel_launch(void* const* d_in, const int* in_sizes, int n_in,
                              void* d_out, int out_size)
{
    const float* x      = (const float*)d_in[0];
    const float* w_qkv  = (const float*)d_in[1];
    const float* b_qkv  = (const float*)d_in[2];
    const float* w_proj = (const float*)d_in[3];
    const float* b_proj = (const float*)d_in[4];
    float* out = (float*)d_out;

    cudaFuncSetAttribute(gemm_f16<0>,
        cudaFuncAttributeMaxDynamicSharedMemorySize, GEMM_SMEM_BYTES);
    cudaFuncSetAttribute(gemm_f16<1>,
        cudaFuncAttributeMaxDynamicSharedMemorySize, GEMM_SMEM_BYTES);
    cudaFuncSetAttribute(attn_f16,
        cudaFuncAttributeMaxDynamicSharedMemorySize, ATTN_SMEM_BYTES);

    prep<<<1024, 256>>>(x, w_qkv, w_proj);
    gemm_f16<0><<<dim3(3*DIMD/128, MTOT/128), 256, GEMM_SMEM_BYTES>>>(b_qkv, nullptr, 3*DIMD);
    attn_f16<<<dim3(SEQ/128, NH, BATCH), 256, ATTN_SMEM_BYTES>>>();
    gemm_f16<1><<<dim3(DIMD/128, MTOT/128), 256, GEMM_SMEM_BYTES>>>(b_proj, out, DIMD);
}

// round 12
// speedup vs baseline: 1.1364x; 1.0212x over previous
#include <cuda_runtime.h>
#include <cuda_fp16.h>
#include <cstdint>

#define DIMD  1024
#define NH    16
#define DH    64
#define BATCH 4
#define SEQ   2048
#define MTOT  (BATCH*SEQ)   // 8192

// Scratch (allocation-free rule: __device__ globals)
__device__ __align__(16) __half g_QH[BATCH*NH*SEQ*DH];   // [B,H,S,Dh]
__device__ __align__(16) __half g_KH[BATCH*NH*SEQ*DH];
__device__ __align__(16) __half g_VH[BATCH*NH*SEQ*DH];
__device__ __align__(16) __half g_AH[MTOT*DIMD];         // attn out, [B,S,D]
__device__ __align__(16) __half g_XH[MTOT*DIMD];         // x as fp16
__device__ __align__(16) uint32_t g_WQP[(DIMD/2)*3*DIMD]; // w_qkv packed k-pairs
__device__ __align__(16) uint32_t g_WPP[(DIMD/2)*DIMD];   // w_proj packed

__device__ __forceinline__ unsigned h2u(__half2 h) {
    return *reinterpret_cast<unsigned*>(&h);
}

__device__ __forceinline__ void mma_f16(
    float& c0, float& c1, float& c2, float& c3,
    unsigned a0, unsigned a1, unsigned a2, unsigned a3,
    unsigned b0, unsigned b1)
{
    asm volatile(
        "mma.sync.aligned.m16n8k16.row.col.f32.f16.f16.f32 "
        "{%0,%1,%2,%3}, {%4,%5,%6,%7}, {%8,%9}, {%0,%1,%2,%3};"
        : "+f"(c0), "+f"(c1), "+f"(c2), "+f"(c3)
        : "r"(a0), "r"(a1), "r"(a2), "r"(a3), "r"(b0), "r"(b1));
}

__device__ __forceinline__ void cpa16(void* dst, const void* src) {
    unsigned s = (unsigned)__cvta_generic_to_shared(dst);
    asm volatile("cp.async.cg.shared.global [%0], [%1], 16;" :: "r"(s), "l"(src));
}
__device__ __forceinline__ void cpa_commit() {
    asm volatile("cp.async.commit_group;");
}
template<int N>
__device__ __forceinline__ void cpa_wait() {
    asm volatile("cp.async.wait_group %0;" :: "n"(N));
}

// ---------------------------------------------------------------------------
// One-time prep: x -> fp16; w_qkv / w_proj -> k-pairwise packed half2
// ---------------------------------------------------------------------------
#define NX4 (MTOT*DIMD/4)            // 2097152
#define NWQ ((DIMD/2)*(3*DIMD/4))    // 512*768
#define NWP ((DIMD/2)*(DIMD/4))      // 512*256

__global__ __launch_bounds__(256)
void prep(const float* __restrict__ x, const float* __restrict__ wq,
          const float* __restrict__ wp)
{
    const int stride = gridDim.x * blockDim.x;
    for (int i = blockIdx.x*blockDim.x + threadIdx.x; i < NX4; i += stride) {
        float4 t = ((const float4*)x)[i];
        uint2 o;
        o.x = h2u(__floats2half2_rn(t.x, t.y));
        o.y = h2u(__floats2half2_rn(t.z, t.w));
        ((uint2*)g_XH)[i] = o;
    }
    for (int i = blockIdx.x*blockDim.x + threadIdx.x; i < NWQ; i += stride) {
        const int k2 = i / 768, n4 = i % 768;
        const float4 a = *(const float4*)(wq + (long)(2*k2  )*3072 + n4*4);
        const float4 b = *(const float4*)(wq + (long)(2*k2+1)*3072 + n4*4);
        uint4 o;
        o.x = h2u(__floats2half2_rn(a.x, b.x));
        o.y = h2u(__floats2half2_rn(a.y, b.y));
        o.z = h2u(__floats2half2_rn(a.z, b.z));
        o.w = h2u(__floats2half2_rn(a.w, b.w));
        ((uint4*)g_WQP)[i] = o;
    }
    for (int i = blockIdx.x*blockDim.x + threadIdx.x; i < NWP; i += stride) {
        const int k2 = i / 256, n4 = i % 256;
        const float4 a = *(const float4*)(wp + (long)(2*k2  )*1024 + n4*4);
        const float4 b = *(const float4*)(wp + (long)(2*k2+1)*1024 + n4*4);
        uint4 o;
        o.x = h2u(__floats2half2_rn(a.x, b.x));
        o.y = h2u(__floats2half2_rn(a.y, b.y));
        o.z = h2u(__floats2half2_rn(a.z, b.z));
        o.w = h2u(__floats2half2_rn(a.w, b.w));
        ((uint4*)g_WPP)[i] = o;
    }
}

// ---------------------------------------------------------------------------
// FP16 GEMM, 3-stage cp.async pipeline, BK=64 halves (32 k-pairs):
// block 128x128, 8 warps (4Mx2N), warp 32x64. 16 iterations of 64 MMAs,
// ONE barrier per chunk. Stage it+2 written into buffer consumed at it-1.
// MODE 0: A=g_XH, B=g_WQP (N=3072) -> Q/K/V fp16
// MODE 1: A=g_AH, B=g_WPP (N=1024) -> out fp32
// ---------------------------------------------------------------------------
#define GA_ST 36                 // 32 k-pair words + 4 pad (banks 4qr+qc)
#define GB_ST 136
#define GA_STAGE (128*GA_ST)     // 4608 words
#define GB_STAGE (32*GB_ST)      // 4352 words
#define STG 3
#define GEMM_SMEM_WORDS (STG*(GA_STAGE+GB_STAGE))   // 26880
#define GEMM_SMEM_BYTES (GEMM_SMEM_WORDS*4)         // 107520

template<int MODE>
__global__ __launch_bounds__(256, 2)
void gemm_f16(const float* __restrict__ bias, float* __restrict__ out, int N)
{
    extern __shared__ uint32_t smw[];
    uint32_t* As2 = smw;                    // [STG][128][36]
    uint32_t* Bs2 = smw + STG*GA_STAGE;     // [STG][32][136]

    const int tid  = threadIdx.x;
    const int lane = tid & 31;
    const int warp = tid >> 5;
    const int warp_m = warp & 3;
    const int warp_n = warp >> 2;
    const int qr = lane >> 2;
    const int qc = lane & 3;

    const int rowStart = blockIdx.y * 128;
    const int colStart = blockIdx.x * 128;
    const __half* Ap = (MODE == 0) ? g_XH : g_AH;
    const uint32_t* Bp = (MODE == 0) ? g_WQP : g_WPP;

    float acc[2][8][4];
    #pragma unroll
    for (int i = 0; i < 2; i++)
        #pragma unroll
        for (int j = 0; j < 8; j++)
            #pragma unroll
            for (int c = 0; c < 4; c++) acc[i][j][c] = 0.f;

    auto load_stage = [&](int s, int k0) {   // k0 in halves, multiple of 64
        uint32_t* as = As2 + s*GA_STAGE;
        uint32_t* bs = Bs2 + s*GB_STAGE;
        #pragma unroll
        for (int i = 0; i < 4; i++) {
            const int q = tid + i*256;       // A: 128 rows x 8 slots (8 halves)
            cpa16(as + (q>>3)*GA_ST + ((q&7)<<2),
                  Ap + (long)(rowStart + (q>>3))*DIMD + k0 + ((q&7)<<3));
        }
        #pragma unroll
        for (int i = 0; i < 4; i++) {
            const int q = tid + i*256;       // B: 32 k2-rows x 32 word-quads
            cpa16(bs + (q>>5)*GB_ST + ((q&31)<<2),
                  Bp + (long)((k0>>1) + (q>>5))*N + colStart + ((q&31)<<2));
        }
    };

    // prologue: stages 0..1 in flight
    #pragma unroll
    for (int s = 0; s < STG-1; s++) { load_stage(s, s*64); cpa_commit(); }

    const int NITER = DIMD / 64;   // 16
    int cur = 0;
    for (int it = 0; it < NITER; it++) {
        cpa_wait<STG-2>();         // stage `it` complete
        __syncthreads();

        const uint32_t* as = As2 + cur*GA_STAGE;
        const uint32_t* bs = Bs2 + cur*GB_STAGE;
        #pragma unroll
        for (int ks = 0; ks < 4; ks++) {
            const int kb2 = ks * 8;
            unsigned a[2][4], b[8][2];
            #pragma unroll
            for (int ma = 0; ma < 2; ma++) {
                const int r = warp_m*32 + ma*16 + qr;
                a[ma][0] = as[(r    )*GA_ST + kb2 + qc    ];
                a[ma][1] = as[(r + 8)*GA_ST + kb2 + qc    ];
                a[ma][2] = as[(r    )*GA_ST + kb2 + qc + 4];
                a[ma][3] = as[(r + 8)*GA_ST + kb2 + qc + 4];
            }
            #pragma unroll
            for (int nb = 0; nb < 8; nb++) {
                const int cc = warp_n*64 + nb*8 + qr;
                b[nb][0] = bs[(kb2 + qc    )*GB_ST + cc];
                b[nb][1] = bs[(kb2 + qc + 4)*GB_ST + cc];
            }
            #pragma unroll
            for (int ma = 0; ma < 2; ma++)
                #pragma unroll
                for (int nb = 0; nb < 8; nb++)
                    mma_f16(acc[ma][nb][0], acc[ma][nb][1],
                            acc[ma][nb][2], acc[ma][nb][3],
                            a[ma][0], a[ma][1], a[ma][2], a[ma][3],
                            b[nb][0], b[nb][1]);
        }

        const int nk = it + STG - 1;
        if (nk < NITER) {
            int nbuf = nk % STG;
            load_stage(nbuf, nk*64);
        }
        cpa_commit();   // unconditional: uniform wait_group arithmetic
        cur = (cur + 1 == STG) ? 0 : cur + 1;
    }

    #pragma unroll
    for (int ma = 0; ma < 2; ma++) {
        const int row0 = rowStart + warp_m*32 + ma*16 + qr;
        #pragma unroll
        for (int nb = 0; nb < 8; nb++) {
            const int col = colStart + warp_n*64 + nb*8 + qc*2;
            const float b0 = bias[col], b1 = bias[col + 1];
            const float v00 = acc[ma][nb][0] + b0, v01 = acc[ma][nb][1] + b1;
            const float v10 = acc[ma][nb][2] + b0, v11 = acc[ma][nb][3] + b1;
            if (MODE == 0) {
                const int part = col >> 10;
                const int dcol = col & 1023;
                const int head = dcol >> 6;
                const int dh   = dcol & 63;
                __half* dst = (part == 0) ? g_QH : (part == 1) ? g_KH : g_VH;
                {
                    const int bb = row0 >> 11, s = row0 & 2047;
                    *(__half2*)(dst + (((bb*NH + head)*SEQ + s) << 6) + dh) =
                        __floats2half2_rn(v00, v01);
                }
                {
                    const int row1 = row0 + 8;
                    const int bb = row1 >> 11, s = row1 & 2047;
                    *(__half2*)(dst + (((bb*NH + head)*SEQ + s) << 6) + dh) =
                        __floats2half2_rn(v10, v11);
                }
            } else {
                *(float2*)(out + (long)row0*N + col) = make_float2(v00, v01);
                *(float2*)(out + (long)(row0 + 8)*N + col) = make_float2(v10, v11);
            }
        }
    }
}

// ---------------------------------------------------------------------------
// FP16 flash attention (unchanged — the proven configuration).
// ---------------------------------------------------------------------------
#define AQ_ST 36
#define KV_STAGE (64*AQ_ST)                       // 2304 words
#define ATTN_SMEM_WORDS (128*AQ_ST + 4*KV_STAGE)  // 13824
#define ATTN_SMEM_BYTES (ATTN_SMEM_WORDS*4)       // 55296

__global__ __launch_bounds__(256, 2)
void attn_f16()
{
    extern __shared__ uint32_t smw[];
    uint32_t* Qs2 = smw;                         // [128][36]
    uint32_t* KsB = smw + 128*AQ_ST;             // [2][64][36]
    uint32_t* VtB = smw + 128*AQ_ST + 2*KV_STAGE;// [2][64][36]  (V^T, key-pairs)

    const int tid  = threadIdx.x;
    const int lane = tid & 31;
    const int warp = tid >> 5;
    const int qr = lane >> 2;
    const int qc = lane & 3;

    const int qt = (int)(gridDim.x - 1) - (int)blockIdx.x;   // heavy tiles first
    const int h = blockIdx.y, b = blockIdx.z;
    const int q0 = qt << 7;

    const long hb = (long)(b*NH + h) * SEQ * DH;
    const __half* Qg = g_QH + hb;
    const __half* Kg = g_KH + hb;
    const __half* Vg = g_VH + hb;

    const __half2 hscale = __float2half2_rn(0.125f);
    #pragma unroll
    for (int i = 0; i < 4; i++) {
        const int q = tid + i*256;
        const int r = q >> 3, w = q & 7;
        uint4 t = *(const uint4*)(Qg + (q0 + r)*DH + w*8);
        __half2* hp = (__half2*)&t;
        hp[0] = __hmul2(hp[0], hscale); hp[1] = __hmul2(hp[1], hscale);
        hp[2] = __hmul2(hp[2], hscale); hp[3] = __hmul2(hp[3], hscale);
        *(uint4*)(&Qs2[r*AQ_ST + w*4]) = t;
    }

    const int vk2  = tid & 31;
    const int vdb  = (tid >> 5) << 3;

    {
        #pragma unroll
        for (int i = 0; i < 2; i++) {
            const int q = tid + i*256;
            const int r = q >> 3, w = q & 7;
            *(uint4*)(&KsB[r*AQ_ST + w*4]) = *(const uint4*)(Kg + r*DH + w*8);
        }
        uint4 lo = *(const uint4*)(Vg + (2*vk2    )*DH + vdb);
        uint4 hi = *(const uint4*)(Vg + (2*vk2 + 1)*DH + vdb);
        const __half* la = (const __half*)&lo;
        const __half* hb2 = (const __half*)&hi;
        #pragma unroll
        for (int j = 0; j < 8; j++)
            VtB[(vdb + j)*AQ_ST + vk2] = h2u(__halves2half2(la[j], hb2[j]));
    }
    __syncthreads();

    float m0 = -1e30f, m1 = -1e30f, l0 = 0.f, l1 = 0.f;
    float o[8][4];
    #pragma unroll
    for (int nb = 0; nb < 8; nb++)
        #pragma unroll
        for (int c = 0; c < 4; c++) o[nb][c] = 0.f;

    const int rowA = warp*16 + qr;
    const int ktiles = 2*qt + 2;

    for (int kt = 0; kt < ktiles; kt++) {
        const int cur = kt & 1;
        const bool more = (kt + 1) < ktiles;
        const uint32_t* Ks = KsB + cur*KV_STAGE;
        const uint32_t* Vt = VtB + cur*KV_STAGE;

        uint4 kreg[2], vlo, vhi;
        if (more) {
            const int k1 = (kt + 1) << 6;
            #pragma unroll
            for (int i = 0; i < 2; i++) {
                const int q = tid + i*256;
                kreg[i] = *(const uint4*)(Kg + (k1 + (q>>3))*DH + (q&7)*8);
            }
            vlo = *(const uint4*)(Vg + (k1 + 2*vk2    )*DH + vdb);
            vhi = *(const uint4*)(Vg + (k1 + 2*vk2 + 1)*DH + vdb);
        }

        float sv[8][4];
        #pragma unroll
        for (int nb = 0; nb < 8; nb++)
            #pragma unroll
            for (int c = 0; c < 4; c++) sv[nb][c] = 0.f;

        #pragma unroll
        for (int ks = 0; ks < 4; ks++) {
            const int kb2 = ks*8;
            const unsigned a0 = Qs2[(rowA    )*AQ_ST + kb2 + qc    ];
            const unsigned a1 = Qs2[(rowA + 8)*AQ_ST + kb2 + qc    ];
            const unsigned a2 = Qs2[(rowA    )*AQ_ST + kb2 + qc + 4];
            const unsigned a3 = Qs2[(rowA + 8)*AQ_ST + kb2 + qc + 4];
            #pragma unroll
            for (int nb = 0; nb < 8; nb++) {
                const unsigned b0 = Ks[(nb*8+qr)*AQ_ST + kb2 + qc    ];
                const unsigned b1 = Ks[(nb*8+qr)*AQ_ST + kb2 + qc + 4];
                mma_f16(sv[nb][0], sv[nb][1], sv[nb][2], sv[nb][3],
                        a0, a1, a2, a3, b0, b1);
            }
        }

        if (kt >= 2*qt) {
            const int k0 = kt << 6;
            const int qg0 = q0 + rowA;
            #pragma unroll
            for (int nb = 0; nb < 8; nb++) {
                const int kg = k0 + nb*8 + 2*qc;
                if (kg     > qg0    ) sv[nb][0] = -1e30f;
                if (kg + 1 > qg0    ) sv[nb][1] = -1e30f;
                if (kg     > qg0 + 8) sv[nb][2] = -1e30f;
                if (kg + 1 > qg0 + 8) sv[nb][3] = -1e30f;
            }
        }

        float mx0 = -1e30f, mx1 = -1e30f;
        #pragma unroll
        for (int nb = 0; nb < 8; nb++) {
            mx0 = fmaxf(mx0, fmaxf(sv[nb][0], sv[nb][1]));
            mx1 = fmaxf(mx1, fmaxf(sv[nb][2], sv[nb][3]));
        }
        mx0 = fmaxf(mx0, __shfl_xor_sync(0xffffffffu, mx0, 1));
        mx0 = fmaxf(mx0, __shfl_xor_sync(0xffffffffu, mx0, 2));
        mx1 = fmaxf(mx1, __shfl_xor_sync(0xffffffffu, mx1, 1));
        mx1 = fmaxf(mx1, __shfl_xor_sync(0xffffffffu, mx1, 2));

        const float m0n = fmaxf(m0, mx0);
        const float m1n = fmaxf(m1, mx1);
        const float al0 = __expf(m0 - m0n);
        const float al1 = __expf(m1 - m1n);
        m0 = m0n; m1 = m1n;

        float ps0 = 0.f, ps1 = 0.f;
        #pragma unroll
        for (int nb = 0; nb < 8; nb++) {
            sv[nb][0] = __expf(sv[nb][0] - m0n);
            sv[nb][1] = __expf(sv[nb][1] - m0n);
            sv[nb][2] = __expf(sv[nb][2] - m1n);
            sv[nb][3] = __expf(sv[nb][3] - m1n);
            ps0 += sv[nb][0] + sv[nb][1];
            ps1 += sv[nb][2] + sv[nb][3];
        }
        ps0 += __shfl_xor_sync(0xffffffffu, ps0, 1);
        ps0 += __shfl_xor_sync(0xffffffffu, ps0, 2);
        ps1 += __shfl_xor_sync(0xffffffffu, ps1, 1);
        ps1 += __shfl_xor_sync(0xffffffffu, ps1, 2);
        l0 = l0*al0 + ps0;
        l1 = l1*al1 + ps1;
        #pragma unroll
        for (int nb = 0; nb < 8; nb++) {
            o[nb][0] *= al0; o[nb][1] *= al0;
            o[nb][2] *= al1; o[nb][3] *= al1;
        }

        #pragma unroll
        for (int ks = 0; ks < 4; ks++) {
            const unsigned a0 = h2u(__floats2half2_rn(sv[2*ks  ][0], sv[2*ks  ][1]));
            const unsigned a1 = h2u(__floats2half2_rn(sv[2*ks  ][2], sv[2*ks  ][3]));
            const unsigned a2 = h2u(__floats2half2_rn(sv[2*ks+1][0], sv[2*ks+1][1]));
            const unsigned a3 = h2u(__floats2half2_rn(sv[2*ks+1][2], sv[2*ks+1][3]));
            #pragma unroll
            for (int nb = 0; nb < 8; nb++) {
                const unsigned b0 = Vt[(nb*8+qr)*AQ_ST + ks*8 + qc    ];
                const unsigned b1 = Vt[(nb*8+qr)*AQ_ST + ks*8 + qc + 4];
                mma_f16(o[nb][0], o[nb][1], o[nb][2], o[nb][3],
                        a0, a1, a2, a3, b0, b1);
            }
        }

        if (more) {
            const int nxt = cur ^ 1;
            uint32_t* KsD = KsB + nxt*KV_STAGE;
            uint32_t* VtD = VtB + nxt*KV_STAGE;
            #pragma unroll
            for (int i = 0; i < 2; i++) {
                const int q = tid + i*256;
                *(uint4*)(&KsD[(q>>3)*AQ_ST + (q&7)*4]) = kreg[i];
            }
            const __half* la = (const __half*)&vlo;
            const __half* hb2 = (const __half*)&vhi;
            #pragma unroll
            for (int j = 0; j < 8; j++)
                VtD[(vdb + j)*AQ_ST + vk2] = h2u(__halves2half2(la[j], hb2[j]));
            __syncthreads();
        }
    }

    const float inv0 = 1.0f / l0;
    const float inv1 = 1.0f / l1;
    const long r0 = (long)(b*SEQ + q0 + rowA);
    #pragma unroll
    for (int nb = 0; nb < 8; nb++) {
        const int col = h*DH + nb*8 + 2*qc;
        *(__half2*)(g_AH + r0*DIMD + col) =
            __floats2half2_rn(o[nb][0]*inv0, o[nb][1]*inv0);
        *(__half2*)(g_AH + (r0 + 8)*DIMD + col) =
            __floats2half2_rn(o[nb][2]*inv1, o[nb][3]*inv1);
    }
}

// ---------------------------------------------------------------------------
extern "C" void kernel_launch(void* const* d_in, const int* in_sizes, int n_in,
                              void* d_out, int out_size)
{
    const float* x      = (const float*)d_in[0];
    const float* w_qkv  = (const float*)d_in[1];
    const float* b_qkv  = (const float*)d_in[2];
    const float* w_proj = (const float*)d_in[3];
    const float* b_proj = (const float*)d_in[4];
    float* out = (float*)d_out;

    cudaFuncSetAttribute(gemm_f16<0>,
        cudaFuncAttributeMaxDynamicSharedMemorySize, GEMM_SMEM_BYTES);
    cudaFuncSetAttribute(gemm_f16<1>,
        cudaFuncAttributeMaxDynamicSharedMemorySize, GEMM_SMEM_BYTES);
    cudaFuncSetAttribute(attn_f16,
        cudaFuncAttributeMaxDynamicSharedMemorySize, ATTN_SMEM_BYTES);

    prep<<<1024, 256>>>(x, w_qkv, w_proj);
    gemm_f16<0><<<dim3(3*DIMD/128, MTOT/128), 256, GEMM_SMEM_BYTES>>>(b_qkv, nullptr, 3*DIMD);
    attn_f16<<<dim3(SEQ/128, NH, BATCH), 256, ATTN_SMEM_BYTES>>>();
    gemm_f16<1><<<dim3(DIMD/128, MTOT/128), 256, GEMM_SMEM_BYTES>>>(b_proj, out, DIMD);
}

// round 14
// speedup vs baseline: 1.1552x; 1.0165x over previous
#include <cuda_runtime.h>
#include <cuda_fp16.h>
#include <cstdint>

#define DIMD  1024
#define NH    16
#define DH    64
#define BATCH 4
#define SEQ   2048
#define MTOT  (BATCH*SEQ)   // 8192

// Scratch (allocation-free rule: __device__ globals)
__device__ __align__(16) __half g_QH[BATCH*NH*SEQ*DH];   // [B,H,S,Dh] (pre-scaled 1/8)
__device__ __align__(16) __half g_KH[BATCH*NH*SEQ*DH];
__device__ __align__(16) __half g_VH[BATCH*NH*SEQ*DH];
__device__ __align__(16) __half g_AH[MTOT*DIMD];         // attn out, [B,S,D]
__device__ __align__(16) __half g_XH[MTOT*DIMD];         // x as fp16
__device__ __align__(16) uint32_t g_WQP[(DIMD/2)*3*DIMD]; // w_qkv packed k-pairs [k2][n]
__device__ __align__(16) uint32_t g_WPP[(DIMD/2)*DIMD];   // w_proj packed [k2][n]

__device__ __forceinline__ unsigned h2u(__half2 h) {
    return *reinterpret_cast<unsigned*>(&h);
}

__device__ __forceinline__ void mma_f16(
    float& c0, float& c1, float& c2, float& c3,
    unsigned a0, unsigned a1, unsigned a2, unsigned a3,
    unsigned b0, unsigned b1)
{
    asm volatile(
        "mma.sync.aligned.m16n8k16.row.col.f32.f16.f16.f32 "
        "{%0,%1,%2,%3}, {%4,%5,%6,%7}, {%8,%9}, {%0,%1,%2,%3};"
        : "+f"(c0), "+f"(c1), "+f"(c2), "+f"(c3)
        : "r"(a0), "r"(a1), "r"(a2), "r"(a3), "r"(b0), "r"(b1));
}

__device__ __forceinline__ void cpa16(void* dst, const void* src) {
    unsigned s = (unsigned)__cvta_generic_to_shared(dst);
    asm volatile("cp.async.cg.shared.global [%0], [%1], 16;" :: "r"(s), "l"(src));
}
__device__ __forceinline__ void cpa_commit() {
    asm volatile("cp.async.commit_group;");
}
template<int N>
__device__ __forceinline__ void cpa_wait() {
    asm volatile("cp.async.wait_group %0;" :: "n"(N));
}

// ---------------------------------------------------------------------------
// One-time prep: x -> fp16; w_qkv / w_proj -> k-pairwise packed half2 [k2][n]
// ---------------------------------------------------------------------------
#define NX4 (MTOT*DIMD/4)            // 2097152
#define NWQ ((DIMD/2)*(3*DIMD/4))    // 512*768
#define NWP ((DIMD/2)*(DIMD/4))      // 512*256

__global__ __launch_bounds__(256)
void prep(const float* __restrict__ x, const float* __restrict__ wq,
          const float* __restrict__ wp)
{
    const int stride = gridDim.x * blockDim.x;
    for (int i = blockIdx.x*blockDim.x + threadIdx.x; i < NX4; i += stride) {
        float4 t = ((const float4*)x)[i];
        uint2 o;
        o.x = h2u(__floats2half2_rn(t.x, t.y));
        o.y = h2u(__floats2half2_rn(t.z, t.w));
        ((uint2*)g_XH)[i] = o;
    }
    for (int i = blockIdx.x*blockDim.x + threadIdx.x; i < NWQ; i += stride) {
        const int k2 = i / 768, n4 = i % 768;
        const float4 a = *(const float4*)(wq + (long)(2*k2  )*3072 + n4*4);
        const float4 b = *(const float4*)(wq + (long)(2*k2+1)*3072 + n4*4);
        uint4 o;
        o.x = h2u(__floats2half2_rn(a.x, b.x));
        o.y = h2u(__floats2half2_rn(a.y, b.y));
        o.z = h2u(__floats2half2_rn(a.z, b.z));
        o.w = h2u(__floats2half2_rn(a.w, b.w));
        ((uint4*)g_WQP)[i] = o;
    }
    for (int i = blockIdx.x*blockDim.x + threadIdx.x; i < NWP; i += stride) {
        const int k2 = i / 256, n4 = i % 256;
        const float4 a = *(const float4*)(wp + (long)(2*k2  )*1024 + n4*4);
        const float4 b = *(const float4*)(wp + (long)(2*k2+1)*1024 + n4*4);
        uint4 o;
        o.x = h2u(__floats2half2_rn(a.x, b.x));
        o.y = h2u(__floats2half2_rn(a.y, b.y));
        o.z = h2u(__floats2half2_rn(a.z, b.z));
        o.w = h2u(__floats2half2_rn(a.w, b.w));
        ((uint4*)g_WPP)[i] = o;
    }
}

// ---------------------------------------------------------------------------
// FP16 GEMM (round-12 exact): 3-stage cp.async, BK=64 halves (32 k-pairs),
// block 128x128, 8 warps (4Mx2N), warp 32x64, scalar fragment LDS.
// MODE 0: A=g_XH, B=g_WQP (N=3072) -> Q(pre-scaled)/K/V fp16
// MODE 1: A=g_AH, B=g_WPP (N=1024) -> out fp32
// ---------------------------------------------------------------------------
#define GA_ST 36
#define GB_ST 136
#define GA_STAGE (128*GA_ST)     // 4608 words
#define GB_STAGE (32*GB_ST)      // 4352 words
#define STG 3
#define GEMM_SMEM_WORDS (STG*(GA_STAGE+GB_STAGE))   // 26880
#define GEMM_SMEM_BYTES (GEMM_SMEM_WORDS*4)         // 107520

template<int MODE>
__global__ __launch_bounds__(256, 2)
void gemm_f16(const float* __restrict__ bias, float* __restrict__ out, int N)
{
    extern __shared__ uint32_t smw[];
    uint32_t* As2 = smw;                    // [STG][128][36]
    uint32_t* Bs2 = smw + STG*GA_STAGE;     // [STG][32][136]

    const int tid  = threadIdx.x;
    const int lane = tid & 31;
    const int warp = tid >> 5;
    const int warp_m = warp & 3;
    const int warp_n = warp >> 2;
    const int qr = lane >> 2;
    const int qc = lane & 3;

    const int rowStart = blockIdx.y * 128;
    const int colStart = blockIdx.x * 128;
    const __half* Ap = (MODE == 0) ? g_XH : g_AH;
    const uint32_t* Bp = (MODE == 0) ? g_WQP : g_WPP;

    float acc[2][8][4];
    #pragma unroll
    for (int i = 0; i < 2; i++)
        #pragma unroll
        for (int j = 0; j < 8; j++)
            #pragma unroll
            for (int c = 0; c < 4; c++) acc[i][j][c] = 0.f;

    auto load_stage = [&](int s, int k0) {   // k0 in halves, multiple of 64
        uint32_t* as = As2 + s*GA_STAGE;
        uint32_t* bs = Bs2 + s*GB_STAGE;
        #pragma unroll
        for (int i = 0; i < 4; i++) {
            const int q = tid + i*256;       // A: 128 rows x 8 slots (8 halves)
            cpa16(as + (q>>3)*GA_ST + ((q&7)<<2),
                  Ap + (long)(rowStart + (q>>3))*DIMD + k0 + ((q&7)<<3));
        }
        #pragma unroll
        for (int i = 0; i < 4; i++) {
            const int q = tid + i*256;       // B: 32 k2-rows x 32 word-quads
            cpa16(bs + (q>>5)*GB_ST + ((q&31)<<2),
                  Bp + (long)((k0>>1) + (q>>5))*N + colStart + ((q&31)<<2));
        }
    };

    #pragma unroll
    for (int s = 0; s < STG-1; s++) { load_stage(s, s*64); cpa_commit(); }

    const int NITER = DIMD / 64;   // 16
    int cur = 0;
    for (int it = 0; it < NITER; it++) {
        cpa_wait<STG-2>();
        __syncthreads();

        const uint32_t* as = As2 + cur*GA_STAGE;
        const uint32_t* bs = Bs2 + cur*GB_STAGE;
        #pragma unroll
        for (int ks = 0; ks < 4; ks++) {
            const int kb2 = ks * 8;
            unsigned a[2][4], b[8][2];
            #pragma unroll
            for (int ma = 0; ma < 2; ma++) {
                const int r = warp_m*32 + ma*16 + qr;
                a[ma][0] = as[(r    )*GA_ST + kb2 + qc    ];
                a[ma][1] = as[(r + 8)*GA_ST + kb2 + qc    ];
                a[ma][2] = as[(r    )*GA_ST + kb2 + qc + 4];
                a[ma][3] = as[(r + 8)*GA_ST + kb2 + qc + 4];
            }
            #pragma unroll
            for (int nb = 0; nb < 8; nb++) {
                const int cc = warp_n*64 + nb*8 + qr;
                b[nb][0] = bs[(kb2 + qc    )*GB_ST + cc];
                b[nb][1] = bs[(kb2 + qc + 4)*GB_ST + cc];
            }
            #pragma unroll
            for (int ma = 0; ma < 2; ma++)
                #pragma unroll
                for (int nb = 0; nb < 8; nb++)
                    mma_f16(acc[ma][nb][0], acc[ma][nb][1],
                            acc[ma][nb][2], acc[ma][nb][3],
                            a[ma][0], a[ma][1], a[ma][2], a[ma][3],
                            b[nb][0], b[nb][1]);
        }

        const int nk = it + STG - 1;
        if (nk < NITER) load_stage(nk % STG, nk*64);
        cpa_commit();
        cur = (cur + 1 == STG) ? 0 : cur + 1;
    }

    #pragma unroll
    for (int ma = 0; ma < 2; ma++) {
        const int row0 = rowStart + warp_m*32 + ma*16 + qr;
        #pragma unroll
        for (int nb = 0; nb < 8; nb++) {
            const int col = colStart + warp_n*64 + nb*8 + qc*2;
            const float b0 = bias[col], b1 = bias[col + 1];
            float v00 = acc[ma][nb][0] + b0, v01 = acc[ma][nb][1] + b1;
            float v10 = acc[ma][nb][2] + b0, v11 = acc[ma][nb][3] + b1;
            if (MODE == 0) {
                const int part = col >> 10;
                if (part == 0) {   // fold attention's 1/sqrt(Dh) into Q
                    v00 *= 0.125f; v01 *= 0.125f;
                    v10 *= 0.125f; v11 *= 0.125f;
                }
                const int dcol = col & 1023;
                const int head = dcol >> 6;
                const int dh   = dcol & 63;
                __half* dst = (part == 0) ? g_QH : (part == 1) ? g_KH : g_VH;
                {
                    const int bb = row0 >> 11, s = row0 & 2047;
                    *(__half2*)(dst + (((bb*NH + head)*SEQ + s) << 6) + dh) =
                        __floats2half2_rn(v00, v01);
                }
                {
                    const int row1 = row0 + 8;
                    const int bb = row1 >> 11, s = row1 & 2047;
                    *(__half2*)(dst + (((bb*NH + head)*SEQ + s) << 6) + dh) =
                        __floats2half2_rn(v10, v11);
                }
            } else {
                *(float2*)(out + (long)row0*N + col) = make_float2(v00, v01);
                *(float2*)(out + (long)(row0 + 8)*N + col) = make_float2(v10, v11);
            }
        }
    }
}

// ---------------------------------------------------------------------------
// FP16 flash attention v3:
//  - Q pre-scaled in gemm<0>; Q tile + K tiles loaded via cp.async (verbatim)
//  - Q fragments hoisted into registers (loop-invariant)
//  - V staged via LDG + in-register key-pair repack (transpose)
//  - double-buffered K/V, ONE barrier per k-tile
// ---------------------------------------------------------------------------
#define AQ_ST 36
#define KV_STAGE (64*AQ_ST)                       // 2304 words
#define ATTN_SMEM_WORDS (128*AQ_ST + 4*KV_STAGE)  // 13824
#define ATTN_SMEM_BYTES (ATTN_SMEM_WORDS*4)       // 55296

__global__ __launch_bounds__(256, 2)
void attn_f16()
{
    extern __shared__ uint32_t smw[];
    uint32_t* Qs2 = smw;                         // [128][36]
    uint32_t* KsB = smw + 128*AQ_ST;             // [2][64][36]
    uint32_t* VtB = smw + 128*AQ_ST + 2*KV_STAGE;// [2][64][36]  (V^T, key-pairs)

    const int tid  = threadIdx.x;
    const int lane = tid & 31;
    const int warp = tid >> 5;
    const int qr = lane >> 2;
    const int qc = lane & 3;

    const int qt = (int)(gridDim.x - 1) - (int)blockIdx.x;   // heavy tiles first
    const int h = blockIdx.y, b = blockIdx.z;
    const int q0 = qt << 7;

    const long hb = (long)(b*NH + h) * SEQ * DH;
    const __half* Qg = g_QH + hb;
    const __half* Kg = g_KH + hb;
    const __half* Vg = g_VH + hb;

    const int vk2 = tid & 31;
    const int vdb = (tid >> 5) << 3;

    // prologue: Q tile (128x32 words) + K tile 0 via cp.async; V0 via LDG
    #pragma unroll
    for (int i = 0; i < 4; i++) {
        const int q = tid + i*256;
        cpa16(Qs2 + (q>>3)*AQ_ST + ((q&7)<<2),
              Qg + (q0 + (q>>3))*DH + ((q&7)<<3));
    }
    #pragma unroll
    for (int i = 0; i < 2; i++) {
        const int q = tid + i*256;
        cpa16(KsB + (q>>3)*AQ_ST + ((q&7)<<2),
              Kg + (q>>3)*DH + ((q&7)<<3));
    }
    cpa_commit();
    {
        uint4 lo = *(const uint4*)(Vg + (2*vk2    )*DH + vdb);
        uint4 hi = *(const uint4*)(Vg + (2*vk2 + 1)*DH + vdb);
        const __half* la = (const __half*)&lo;
        const __half* ha = (const __half*)&hi;
        #pragma unroll
        for (int j = 0; j < 8; j++)
            VtB[(vdb + j)*AQ_ST + vk2] = h2u(__halves2half2(la[j], ha[j]));
    }
    cpa_wait<0>();
    __syncthreads();

    // hoist Q fragments (loop-invariant): qa[ks][0..3]
    const int rowA = warp*16 + qr;
    unsigned qa[4][4];
    #pragma unroll
    for (int ks = 0; ks < 4; ks++) {
        const int kb2 = ks*8;
        qa[ks][0] = Qs2[(rowA    )*AQ_ST + kb2 + qc    ];
        qa[ks][1] = Qs2[(rowA + 8)*AQ_ST + kb2 + qc    ];
        qa[ks][2] = Qs2[(rowA    )*AQ_ST + kb2 + qc + 4];
        qa[ks][3] = Qs2[(rowA + 8)*AQ_ST + kb2 + qc + 4];
    }

    float m0 = -1e30f, m1 = -1e30f, l0 = 0.f, l1 = 0.f;
    float o[8][4];
    #pragma unroll
    for (int nb = 0; nb < 8; nb++)
        #pragma unroll
        for (int c = 0; c < 4; c++) o[nb][c] = 0.f;

    const int ktiles = 2*qt + 2;

    for (int kt = 0; kt < ktiles; kt++) {
        const int cur = kt & 1;
        const bool more = (kt + 1) < ktiles;
        const uint32_t* Ks = KsB + cur*KV_STAGE;
        const uint32_t* Vt = VtB + cur*KV_STAGE;

        // issue next K tile via cp.async (buffer nxt consumed at kt-1 -> safe);
        // stage next V in registers
        uint4 vlo, vhi;
        if (more) {
            const int k1 = (kt + 1) << 6;
            const int nxt = cur ^ 1;
            uint32_t* KsD = KsB + nxt*KV_STAGE;
            #pragma unroll
            for (int i = 0; i < 2; i++) {
                const int q = tid + i*256;
                cpa16(KsD + (q>>3)*AQ_ST + ((q&7)<<2),
                      Kg + (k1 + (q>>3))*DH + ((q&7)<<3));
            }
            vlo = *(const uint4*)(Vg + (k1 + 2*vk2    )*DH + vdb);
            vhi = *(const uint4*)(Vg + (k1 + 2*vk2 + 1)*DH + vdb);
        }
        cpa_commit();

        // S = Q K^T (Q fragments in registers)
        float sv[8][4];
        #pragma unroll
        for (int nb = 0; nb < 8; nb++)
            #pragma unroll
            for (int c = 0; c < 4; c++) sv[nb][c] = 0.f;

        #pragma unroll
        for (int ks = 0; ks < 4; ks++) {
            const int kb2 = ks*8;
            #pragma unroll
            for (int nb = 0; nb < 8; nb++) {
                const unsigned b0 = Ks[(nb*8+qr)*AQ_ST + kb2 + qc    ];
                const unsigned b1 = Ks[(nb*8+qr)*AQ_ST + kb2 + qc + 4];
                mma_f16(sv[nb][0], sv[nb][1], sv[nb][2], sv[nb][3],
                        qa[ks][0], qa[ks][1], qa[ks][2], qa[ks][3], b0, b1);
            }
        }

        // causal mask (two diagonal k-tiles only)
        if (kt >= 2*qt) {
            const int k0 = kt << 6;
            const int qg0 = q0 + rowA;
            #pragma unroll
            for (int nb = 0; nb < 8; nb++) {
                const int kg = k0 + nb*8 + 2*qc;
                if (kg     > qg0    ) sv[nb][0] = -1e30f;
                if (kg + 1 > qg0    ) sv[nb][1] = -1e30f;
                if (kg     > qg0 + 8) sv[nb][2] = -1e30f;
                if (kg + 1 > qg0 + 8) sv[nb][3] = -1e30f;
            }
        }

        // online softmax
        float mx0 = -1e30f, mx1 = -1e30f;
        #pragma unroll
        for (int nb = 0; nb < 8; nb++) {
            mx0 = fmaxf(mx0, fmaxf(sv[nb][0], sv[nb][1]));
            mx1 = fmaxf(mx1, fmaxf(sv[nb][2], sv[nb][3]));
        }
        mx0 = fmaxf(mx0, __shfl_xor_sync(0xffffffffu, mx0, 1));
        mx0 = fmaxf(mx0, __shfl_xor_sync(0xffffffffu, mx0, 2));
        mx1 = fmaxf(mx1, __shfl_xor_sync(0xffffffffu, mx1, 1));
        mx1 = fmaxf(mx1, __shfl_xor_sync(0xffffffffu, mx1, 2));

        const float m0n = fmaxf(m0, mx0);
        const float m1n = fmaxf(m1, mx1);
        const float al0 = __expf(m0 - m0n);
        const float al1 = __expf(m1 - m1n);
        m0 = m0n; m1 = m1n;

        float ps0 = 0.f, ps1 = 0.f;
        #pragma unroll
        for (int nb = 0; nb < 8; nb++) {
            sv[nb][0] = __expf(sv[nb][0] - m0n);
            sv[nb][1] = __expf(sv[nb][1] - m0n);
            sv[nb][2] = __expf(sv[nb][2] - m1n);
            sv[nb][3] = __expf(sv[nb][3] - m1n);
            ps0 += sv[nb][0] + sv[nb][1];
            ps1 += sv[nb][2] + sv[nb][3];
        }
        ps0 += __shfl_xor_sync(0xffffffffu, ps0, 1);
        ps0 += __shfl_xor_sync(0xffffffffu, ps0, 2);
        ps1 += __shfl_xor_sync(0xffffffffu, ps1, 1);
        ps1 += __shfl_xor_sync(0xffffffffu, ps1, 2);
        l0 = l0*al0 + ps0;
        l1 = l1*al1 + ps1;
        #pragma unroll
        for (int nb = 0; nb < 8; nb++) {
            o[nb][0] *= al0; o[nb][1] *= al0;
            o[nb][2] *= al1; o[nb][3] *= al1;
        }

        // O += P @ V : P fragments are LOCAL
        #pragma unroll
        for (int ks = 0; ks < 4; ks++) {
            const unsigned a0 = h2u(__floats2half2_rn(sv[2*ks  ][0], sv[2*ks  ][1]));
            const unsigned a1 = h2u(__floats2half2_rn(sv[2*ks  ][2], sv[2*ks  ][3]));
            const unsigned a2 = h2u(__floats2half2_rn(sv[2*ks+1][0], sv[2*ks+1][1]));
            const unsigned a3 = h2u(__floats2half2_rn(sv[2*ks+1][2], sv[2*ks+1][3]));
            #pragma unroll
            for (int nb = 0; nb < 8; nb++) {
                const unsigned b0 = Vt[(nb*8+qr)*AQ_ST + ks*8 + qc    ];
                const unsigned b1 = Vt[(nb*8+qr)*AQ_ST + ks*8 + qc + 4];
                mma_f16(o[nb][0], o[nb][1], o[nb][2], o[nb][3],
                        a0, a1, a2, a3, b0, b1);
            }
        }

        // drain K cp.async, store staged V, single barrier
        if (more) {
            const int nxt = cur ^ 1;
            uint32_t* VtD = VtB + nxt*KV_STAGE;
            const __half* la = (const __half*)&vlo;
            const __half* ha = (const __half*)&vhi;
            #pragma unroll
            for (int j = 0; j < 8; j++)
                VtD[(vdb + j)*AQ_ST + vk2] = h2u(__halves2half2(la[j], ha[j]));
            cpa_wait<0>();
            __syncthreads();
        }
    }

    const float inv0 = 1.0f / l0;
    const float inv1 = 1.0f / l1;
    const long r0 = (long)(b*SEQ + q0 + rowA);
    #pragma unroll
    for (int nb = 0; nb < 8; nb++) {
        const int col = h*DH + nb*8 + 2*qc;
        *(__half2*)(g_AH + r0*DIMD + col) =
            __floats2half2_rn(o[nb][0]*inv0, o[nb][1]*inv0);
        *(__half2*)(g_AH + (r0 + 8)*DIMD + col) =
            __floats2half2_rn(o[nb][2]*inv1, o[nb][3]*inv1);
    }
}

// ---------------------------------------------------------------------------
extern "C" void kernel_launch(void* const* d_in, const int* in_sizes, int n_in,
                              void* d_out, int out_size)
{
    const float* x      = (const float*)d_in[0];
    const float* w_qkv  = (const float*)d_in[1];
    const float* b_qkv  = (const float*)d_in[2];
    const float* w_proj = (const float*)d_in[3];
    const float* b_proj = (const float*)d_in[4];
    float* out = (float*)d_out;

    cudaFuncSetAttribute(gemm_f16<0>,
        cudaFuncAttributeMaxDynamicSharedMemorySize, GEMM_SMEM_BYTES);
    cudaFuncSetAttribute(gemm_f16<1>,
        cudaFuncAttributeMaxDynamicSharedMemorySize, GEMM_SMEM_BYTES);
    cudaFuncSetAttribute(attn_f16,
        cudaFuncAttributeMaxDynamicSharedMemorySize, ATTN_SMEM_BYTES);

    prep<<<1024, 256>>>(x, w_qkv, w_proj);
    gemm_f16<0><<<dim3(3*DIMD/128, MTOT/128), 256, GEMM_SMEM_BYTES>>>(b_qkv, nullptr, 3*DIMD);
    attn_f16<<<dim3(SEQ/128, NH, BATCH), 256, ATTN_SMEM_BYTES>>>();
    gemm_f16<1><<<dim3(DIMD/128, MTOT/128), 256, GEMM_SMEM_BYTES>>>(b_proj, out, DIMD);
}

// round 15
// speedup vs baseline: 1.2616x; 1.0921x over previous
#include <cuda_runtime.h>
#include <cuda_fp16.h>
#include <cstdint>

#define DIMD  1024
#define NH    16
#define DH    64
#define BATCH 4
#define SEQ   2048
#define MTOT  (BATCH*SEQ)   // 8192

// Scratch (allocation-free rule: __device__ globals)
__device__ __align__(16) __half g_QH[BATCH*NH*SEQ*DH];   // [B,H,S,Dh] (pre-scaled 1/8)
__device__ __align__(16) __half g_KH[BATCH*NH*SEQ*DH];
__device__ __align__(16) uint32_t g_VTP[BATCH*NH*DH*(SEQ/2)]; // V^T key-pairs [B,H,Dh,S/2]
__device__ __align__(16) __half g_AH[MTOT*DIMD];         // attn out, [B,S,D]
__device__ __align__(16) __half g_XH[MTOT*DIMD];         // x as fp16
__device__ __align__(16) uint32_t g_WQP[(DIMD/2)*3*DIMD]; // w_qkv packed k-pairs [k2][n]
__device__ __align__(16) uint32_t g_WPP[(DIMD/2)*DIMD];   // w_proj packed [k2][n]

__device__ __forceinline__ unsigned h2u(__half2 h) {
    return *reinterpret_cast<unsigned*>(&h);
}

__device__ __forceinline__ void mma_f16(
    float& c0, float& c1, float& c2, float& c3,
    unsigned a0, unsigned a1, unsigned a2, unsigned a3,
    unsigned b0, unsigned b1)
{
    asm volatile(
        "mma.sync.aligned.m16n8k16.row.col.f32.f16.f16.f32 "
        "{%0,%1,%2,%3}, {%4,%5,%6,%7}, {%8,%9}, {%0,%1,%2,%3};"
        : "+f"(c0), "+f"(c1), "+f"(c2), "+f"(c3)
        : "r"(a0), "r"(a1), "r"(a2), "r"(a3), "r"(b0), "r"(b1));
}

__device__ __forceinline__ void cpa16(void* dst, const void* src) {
    unsigned s = (unsigned)__cvta_generic_to_shared(dst);
    asm volatile("cp.async.cg.shared.global [%0], [%1], 16;" :: "r"(s), "l"(src));
}
__device__ __forceinline__ void cpa_commit() {
    asm volatile("cp.async.commit_group;");
}
template<int N>
__device__ __forceinline__ void cpa_wait() {
    asm volatile("cp.async.wait_group %0;" :: "n"(N));
}

// ---------------------------------------------------------------------------
// One-time prep: x -> fp16; w_qkv / w_proj -> k-pairwise packed half2 [k2][n]
// ---------------------------------------------------------------------------
#define NX4 (MTOT*DIMD/4)            // 2097152
#define NWQ ((DIMD/2)*(3*DIMD/4))    // 512*768
#define NWP ((DIMD/2)*(DIMD/4))      // 512*256

__global__ __launch_bounds__(256)
void prep(const float* __restrict__ x, const float* __restrict__ wq,
          const float* __restrict__ wp)
{
    const int stride = gridDim.x * blockDim.x;
    for (int i = blockIdx.x*blockDim.x + threadIdx.x; i < NX4; i += stride) {
        float4 t = ((const float4*)x)[i];
        uint2 o;
        o.x = h2u(__floats2half2_rn(t.x, t.y));
        o.y = h2u(__floats2half2_rn(t.z, t.w));
        ((uint2*)g_XH)[i] = o;
    }
    for (int i = blockIdx.x*blockDim.x + threadIdx.x; i < NWQ; i += stride) {
        const int k2 = i / 768, n4 = i % 768;
        const float4 a = *(const float4*)(wq + (long)(2*k2  )*3072 + n4*4);
        const float4 b = *(const float4*)(wq + (long)(2*k2+1)*3072 + n4*4);
        uint4 o;
        o.x = h2u(__floats2half2_rn(a.x, b.x));
        o.y = h2u(__floats2half2_rn(a.y, b.y));
        o.z = h2u(__floats2half2_rn(a.z, b.z));
        o.w = h2u(__floats2half2_rn(a.w, b.w));
        ((uint4*)g_WQP)[i] = o;
    }
    for (int i = blockIdx.x*blockDim.x + threadIdx.x; i < NWP; i += stride) {
        const int k2 = i / 256, n4 = i % 256;
        const float4 a = *(const float4*)(wp + (long)(2*k2  )*1024 + n4*4);
        const float4 b = *(const float4*)(wp + (long)(2*k2+1)*1024 + n4*4);
        uint4 o;
        o.x = h2u(__floats2half2_rn(a.x, b.x));
        o.y = h2u(__floats2half2_rn(a.y, b.y));
        o.z = h2u(__floats2half2_rn(a.z, b.z));
        o.w = h2u(__floats2half2_rn(a.w, b.w));
        ((uint4*)g_WPP)[i] = o;
    }
}

// ---------------------------------------------------------------------------
// FP16 GEMM: 3-stage cp.async, BK=64 halves, block 128x128, 8 warps (4Mx2N),
// warp 32x64, scalar fragment LDS.
// MODE 0: A=g_XH, B=g_WQP (N=3072) -> Q(pre-scaled)/K fp16, V^T packed
// MODE 1: A=g_AH, B=g_WPP (N=1024) -> out fp32
// ---------------------------------------------------------------------------
#define GA_ST 36
#define GB_ST 136
#define GA_STAGE (128*GA_ST)     // 4608 words
#define GB_STAGE (32*GB_ST)      // 4352 words
#define STG 3
#define GEMM_SMEM_WORDS (STG*(GA_STAGE+GB_STAGE))   // 26880
#define GEMM_SMEM_BYTES (GEMM_SMEM_WORDS*4)         // 107520

template<int MODE>
__global__ __launch_bounds__(256, 2)
void gemm_f16(const float* __restrict__ bias, float* __restrict__ out, int N)
{
    extern __shared__ uint32_t smw[];
    uint32_t* As2 = smw;                    // [STG][128][36]
    uint32_t* Bs2 = smw + STG*GA_STAGE;     // [STG][32][136]

    const int tid  = threadIdx.x;
    const int lane = tid & 31;
    const int warp = tid >> 5;
    const int warp_m = warp & 3;
    const int warp_n = warp >> 2;
    const int qr = lane >> 2;
    const int qc = lane & 3;

    const int rowStart = blockIdx.y * 128;
    const int colStart = blockIdx.x * 128;
    const __half* Ap = (MODE == 0) ? g_XH : g_AH;
    const uint32_t* Bp = (MODE == 0) ? g_WQP : g_WPP;

    float acc[2][8][4];
    #pragma unroll
    for (int i = 0; i < 2; i++)
        #pragma unroll
        for (int j = 0; j < 8; j++)
            #pragma unroll
            for (int c = 0; c < 4; c++) acc[i][j][c] = 0.f;

    auto load_stage = [&](int s, int k0) {   // k0 in halves, multiple of 64
        uint32_t* as = As2 + s*GA_STAGE;
        uint32_t* bs = Bs2 + s*GB_STAGE;
        #pragma unroll
        for (int i = 0; i < 4; i++) {
            const int q = tid + i*256;       // A: 128 rows x 8 slots (8 halves)
            cpa16(as + (q>>3)*GA_ST + ((q&7)<<2),
                  Ap + (long)(rowStart + (q>>3))*DIMD + k0 + ((q&7)<<3));
        }
        #pragma unroll
        for (int i = 0; i < 4; i++) {
            const int q = tid + i*256;       // B: 32 k2-rows x 32 word-quads
            cpa16(bs + (q>>5)*GB_ST + ((q&31)<<2),
                  Bp + (long)((k0>>1) + (q>>5))*N + colStart + ((q&31)<<2));
        }
    };

    #pragma unroll
    for (int s = 0; s < STG-1; s++) { load_stage(s, s*64); cpa_commit(); }

    const int NITER = DIMD / 64;   // 16
    int cur = 0;
    for (int it = 0; it < NITER; it++) {
        cpa_wait<STG-2>();
        __syncthreads();

        const uint32_t* as = As2 + cur*GA_STAGE;
        const uint32_t* bs = Bs2 + cur*GB_STAGE;
        #pragma unroll
        for (int ks = 0; ks < 4; ks++) {
            const int kb2 = ks * 8;
            unsigned a[2][4], b[8][2];
            #pragma unroll
            for (int ma = 0; ma < 2; ma++) {
                const int r = warp_m*32 + ma*16 + qr;
                a[ma][0] = as[(r    )*GA_ST + kb2 + qc    ];
                a[ma][1] = as[(r + 8)*GA_ST + kb2 + qc    ];
                a[ma][2] = as[(r    )*GA_ST + kb2 + qc + 4];
                a[ma][3] = as[(r + 8)*GA_ST + kb2 + qc + 4];
            }
            #pragma unroll
            for (int nb = 0; nb < 8; nb++) {
                const int cc = warp_n*64 + nb*8 + qr;
                b[nb][0] = bs[(kb2 + qc    )*GB_ST + cc];
                b[nb][1] = bs[(kb2 + qc + 4)*GB_ST + cc];
            }
            #pragma unroll
            for (int ma = 0; ma < 2; ma++)
                #pragma unroll
                for (int nb = 0; nb < 8; nb++)
                    mma_f16(acc[ma][nb][0], acc[ma][nb][1],
                            acc[ma][nb][2], acc[ma][nb][3],
                            a[ma][0], a[ma][1], a[ma][2], a[ma][3],
                            b[nb][0], b[nb][1]);
        }

        const int nk = it + STG - 1;
        if (nk < NITER) load_stage(nk % STG, nk*64);
        cpa_commit();
        cur = (cur + 1 == STG) ? 0 : cur + 1;
    }

    #pragma unroll
    for (int ma = 0; ma < 2; ma++) {
        const int row0 = rowStart + warp_m*32 + ma*16 + qr;
        #pragma unroll
        for (int nb = 0; nb < 8; nb++) {
            const int col = colStart + warp_n*64 + nb*8 + qc*2;
            const float b0 = bias[col], b1 = bias[col + 1];
            float v00 = acc[ma][nb][0] + b0, v01 = acc[ma][nb][1] + b1;
            float v10 = acc[ma][nb][2] + b0, v11 = acc[ma][nb][3] + b1;
            if (MODE == 0) {
                const int part = col >> 10;    // uniform per block
                const int dcol = col & 1023;
                const int head = dcol >> 6;
                const int dh   = dcol & 63;
                if (part == 2) {
                    // V: write transposed key-pair words to g_VTP[b,h][d][s/2]
                    // partner lane (+4) holds rows row0+1 / row0+9
                    const float p00 = __shfl_down_sync(0xffffffffu, v00, 4);
                    const float p01 = __shfl_down_sync(0xffffffffu, v01, 4);
                    const float p10 = __shfl_down_sync(0xffffffffu, v10, 4);
                    const float p11 = __shfl_down_sync(0xffffffffu, v11, 4);
                    if (!(qr & 1)) {
                        const int bb = row0 >> 11, s = row0 & 2047;
                        uint32_t* vb = g_VTP +
                            (long)((bb*NH + head)*DH + dh)*(SEQ/2) + (s >> 1);
                        vb[0]              = h2u(__floats2half2_rn(v00, p00));
                        vb[SEQ/2]          = h2u(__floats2half2_rn(v01, p01));
                        vb[4]              = h2u(__floats2half2_rn(v10, p10));
                        vb[SEQ/2 + 4]      = h2u(__floats2half2_rn(v11, p11));
                    }
                } else {
                    if (part == 0) {   // fold attention's 1/sqrt(Dh) into Q
                        v00 *= 0.125f; v01 *= 0.125f;
                        v10 *= 0.125f; v11 *= 0.125f;
                    }
                    __half* dst = (part == 0) ? g_QH : g_KH;
                    {
                        const int bb = row0 >> 11, s = row0 & 2047;
                        *(__half2*)(dst + (((bb*NH + head)*SEQ + s) << 6) + dh) =
                            __floats2half2_rn(v00, v01);
                    }
                    {
                        const int row1 = row0 + 8;
                        const int bb = row1 >> 11, s = row1 & 2047;
                        *(__half2*)(dst + (((bb*NH + head)*SEQ + s) << 6) + dh) =
                            __floats2half2_rn(v10, v11);
                    }
                }
            } else {
                *(float2*)(out + (long)row0*N + col) = make_float2(v00, v01);
                *(float2*)(out + (long)(row0 + 8)*N + col) = make_float2(v10, v11);
            }
        }
    }
}

// ---------------------------------------------------------------------------
// FP16 flash attention v4: Q/K/V ALL loaded via cp.async (V pre-transposed
// globally). Q fragments hoisted. Double-buffered K/V, ONE barrier per tile.
// ---------------------------------------------------------------------------
#define AQ_ST 36
#define KV_STAGE (64*AQ_ST)                       // 2304 words
#define ATTN_SMEM_WORDS (128*AQ_ST + 4*KV_STAGE)  // 13824
#define ATTN_SMEM_BYTES (ATTN_SMEM_WORDS*4)       // 55296

__global__ __launch_bounds__(256, 2)
void attn_f16()
{
    extern __shared__ uint32_t smw[];
    uint32_t* Qs2 = smw;                         // [128][36]
    uint32_t* KsB = smw + 128*AQ_ST;             // [2][64][36]
    uint32_t* VtB = smw + 128*AQ_ST + 2*KV_STAGE;// [2][64][36]  (V^T, key-pairs)

    const int tid  = threadIdx.x;
    const int lane = tid & 31;
    const int warp = tid >> 5;
    const int qr = lane >> 2;
    const int qc = lane & 3;

    const int qt = (int)(gridDim.x - 1) - (int)blockIdx.x;   // heavy tiles first
    const int h = blockIdx.y, b = blockIdx.z;
    const int q0 = qt << 7;

    const long hb = (long)(b*NH + h) * SEQ * DH;
    const __half* Qg = g_QH + hb;
    const __half* Kg = g_KH + hb;
    const uint32_t* Vp = g_VTP + (long)(b*NH + h) * DH * (SEQ/2);

    // prologue: Q tile + K tile 0 + V tile 0, all cp.async
    #pragma unroll
    for (int i = 0; i < 4; i++) {
        const int q = tid + i*256;
        cpa16(Qs2 + (q>>3)*AQ_ST + ((q&7)<<2),
              Qg + (q0 + (q>>3))*DH + ((q&7)<<3));
    }
    #pragma unroll
    for (int i = 0; i < 2; i++) {
        const int q = tid + i*256;
        cpa16(KsB + (q>>3)*AQ_ST + ((q&7)<<2),
              Kg + (q>>3)*DH + ((q&7)<<3));
        cpa16(VtB + (q>>3)*AQ_ST + ((q&7)<<2),
              Vp + (q>>3)*(SEQ/2) + ((q&7)<<2));
    }
    cpa_commit();
    cpa_wait<0>();
    __syncthreads();

    // hoist Q fragments (loop-invariant)
    const int rowA = warp*16 + qr;
    unsigned qa[4][4];
    #pragma unroll
    for (int ks = 0; ks < 4; ks++) {
        const int kb2 = ks*8;
        qa[ks][0] = Qs2[(rowA    )*AQ_ST + kb2 + qc    ];
        qa[ks][1] = Qs2[(rowA + 8)*AQ_ST + kb2 + qc    ];
        qa[ks][2] = Qs2[(rowA    )*AQ_ST + kb2 + qc + 4];
        qa[ks][3] = Qs2[(rowA + 8)*AQ_ST + kb2 + qc + 4];
    }

    float m0 = -1e30f, m1 = -1e30f, l0 = 0.f, l1 = 0.f;
    float o[8][4];
    #pragma unroll
    for (int nb = 0; nb < 8; nb++)
        #pragma unroll
        for (int c = 0; c < 4; c++) o[nb][c] = 0.f;

    const int ktiles = 2*qt + 2;

    for (int kt = 0; kt < ktiles; kt++) {
        const int cur = kt & 1;
        const bool more = (kt + 1) < ktiles;
        const uint32_t* Ks = KsB + cur*KV_STAGE;
        const uint32_t* Vt = VtB + cur*KV_STAGE;

        // issue next K+V tiles via cp.async (buffer nxt consumed at kt-1)
        if (more) {
            const int k1 = (kt + 1) << 6;
            const int nxt = cur ^ 1;
            uint32_t* KsD = KsB + nxt*KV_STAGE;
            uint32_t* VtD = VtB + nxt*KV_STAGE;
            #pragma unroll
            for (int i = 0; i < 2; i++) {
                const int q = tid + i*256;
                cpa16(KsD + (q>>3)*AQ_ST + ((q&7)<<2),
                      Kg + (k1 + (q>>3))*DH + ((q&7)<<3));
                cpa16(VtD + (q>>3)*AQ_ST + ((q&7)<<2),
                      Vp + (q>>3)*(SEQ/2) + (k1>>1) + ((q&7)<<2));
            }
        }
        cpa_commit();

        // S = Q K^T (Q fragments in registers)
        float sv[8][4];
        #pragma unroll
        for (int nb = 0; nb < 8; nb++)
            #pragma unroll
            for (int c = 0; c < 4; c++) sv[nb][c] = 0.f;

        #pragma unroll
        for (int ks = 0; ks < 4; ks++) {
            const int kb2 = ks*8;
            #pragma unroll
            for (int nb = 0; nb < 8; nb++) {
                const unsigned b0 = Ks[(nb*8+qr)*AQ_ST + kb2 + qc    ];
                const unsigned b1 = Ks[(nb*8+qr)*AQ_ST + kb2 + qc + 4];
                mma_f16(sv[nb][0], sv[nb][1], sv[nb][2], sv[nb][3],
                        qa[ks][0], qa[ks][1], qa[ks][2], qa[ks][3], b0, b1);
            }
        }

        // causal mask (two diagonal k-tiles only)
        if (kt >= 2*qt) {
            const int k0 = kt << 6;
            const int qg0 = q0 + rowA;
            #pragma unroll
            for (int nb = 0; nb < 8; nb++) {
                const int kg = k0 + nb*8 + 2*qc;
                if (kg     > qg0    ) sv[nb][0] = -1e30f;
                if (kg + 1 > qg0    ) sv[nb][1] = -1e30f;
                if (kg     > qg0 + 8) sv[nb][2] = -1e30f;
                if (kg + 1 > qg0 + 8) sv[nb][3] = -1e30f;
            }
        }

        // online softmax
        float mx0 = -1e30f, mx1 = -1e30f;
        #pragma unroll
        for (int nb = 0; nb < 8; nb++) {
            mx0 = fmaxf(mx0, fmaxf(sv[nb][0], sv[nb][1]));
            mx1 = fmaxf(mx1, fmaxf(sv[nb][2], sv[nb][3]));
        }
        mx0 = fmaxf(mx0, __shfl_xor_sync(0xffffffffu, mx0, 1));
        mx0 = fmaxf(mx0, __shfl_xor_sync(0xffffffffu, mx0, 2));
        mx1 = fmaxf(mx1, __shfl_xor_sync(0xffffffffu, mx1, 1));
        mx1 = fmaxf(mx1, __shfl_xor_sync(0xffffffffu, mx1, 2));

        const float m0n = fmaxf(m0, mx0);
        const float m1n = fmaxf(m1, mx1);
        const float al0 = __expf(m0 - m0n);
        const float al1 = __expf(m1 - m1n);
        m0 = m0n; m1 = m1n;

        float ps0 = 0.f, ps1 = 0.f;
        #pragma unroll
        for (int nb = 0; nb < 8; nb++) {
            sv[nb][0] = __expf(sv[nb][0] - m0n);
            sv[nb][1] = __expf(sv[nb][1] - m0n);
            sv[nb][2] = __expf(sv[nb][2] - m1n);
            sv[nb][3] = __expf(sv[nb][3] - m1n);
            ps0 += sv[nb][0] + sv[nb][1];
            ps1 += sv[nb][2] + sv[nb][3];
        }
        ps0 += __shfl_xor_sync(0xffffffffu, ps0, 1);
        ps0 += __shfl_xor_sync(0xffffffffu, ps0, 2);
        ps1 += __shfl_xor_sync(0xffffffffu, ps1, 1);
        ps1 += __shfl_xor_sync(0xffffffffu, ps1, 2);
        l0 = l0*al0 + ps0;
        l1 = l1*al1 + ps1;
        #pragma unroll
        for (int nb = 0; nb < 8; nb++) {
            o[nb][0] *= al0; o[nb][1] *= al0;
            o[nb][2] *= al1; o[nb][3] *= al1;
        }

        // O += P @ V : P fragments are LOCAL
        #pragma unroll
        for (int ks = 0; ks < 4; ks++) {
            const unsigned a0 = h2u(__floats2half2_rn(sv[2*ks  ][0], sv[2*ks  ][1]));
            const unsigned a1 = h2u(__floats2half2_rn(sv[2*ks  ][2], sv[2*ks  ][3]));
            const unsigned a2 = h2u(__floats2half2_rn(sv[2*ks+1][0], sv[2*ks+1][1]));
            const unsigned a3 = h2u(__floats2half2_rn(sv[2*ks+1][2], sv[2*ks+1][3]));
            #pragma unroll
            for (int nb = 0; nb < 8; nb++) {
                const unsigned b0 = Vt[(nb*8+qr)*AQ_ST + ks*8 + qc    ];
                const unsigned b1 = Vt[(nb*8+qr)*AQ_ST + ks*8 + qc + 4];
                mma_f16(o[nb][0], o[nb][1], o[nb][2], o[nb][3],
                        a0, a1, a2, a3, b0, b1);
            }
        }

        if (more) {
            cpa_wait<0>();
            __syncthreads();
        }
    }

    const float inv0 = 1.0f / l0;
    const float inv1 = 1.0f / l1;
    const long r0 = (long)(b*SEQ + q0 + rowA);
    #pragma unroll
    for (int nb = 0; nb < 8; nb++) {
        const int col = h*DH + nb*8 + 2*qc;
        *(__half2*)(g_AH + r0*DIMD + col) =
            __floats2half2_rn(o[nb][0]*inv0, o[nb][1]*inv0);
        *(__half2*)(g_AH + (r0 + 8)*DIMD + col) =
            __floats2half2_rn(o[nb][2]*inv1, o[nb][3]*inv1);
    }
}

// ---------------------------------------------------------------------------
extern "C" void kernel_launch(void* const* d_in, const int* in_sizes, int n_in,
                              void* d_out, int out_size)
{
    const float* x      = (const float*)d_in[0];
    const float* w_qkv  = (const float*)d_in[1];
    const float* b_qkv  = (const float*)d_in[2];
    const float* w_proj = (const float*)d_in[3];
    const float* b_proj = (const float*)d_in[4];
    float* out = (float*)d_out;

    cudaFuncSetAttribute(gemm_f16<0>,
        cudaFuncAttributeMaxDynamicSharedMemorySize, GEMM_SMEM_BYTES);
    cudaFuncSetAttribute(gemm_f16<1>,
        cudaFuncAttributeMaxDynamicSharedMemorySize, GEMM_SMEM_BYTES);
    cudaFuncSetAttribute(attn_f16,
        cudaFuncAttributeMaxDynamicSharedMemorySize, ATTN_SMEM_BYTES);

    prep<<<1024, 256>>>(x, w_qkv, w_proj);
    gemm_f16<0><<<dim3(3*DIMD/128, MTOT/128), 256, GEMM_SMEM_BYTES>>>(b_qkv, nullptr, 3*DIMD);
    attn_f16<<<dim3(SEQ/128, NH, BATCH), 256, ATTN_SMEM_BYTES>>>();
    gemm_f16<1><<<dim3(DIMD/128, MTOT/128), 256, GEMM_SMEM_BYTES>>>(b_proj, out, DIMD);
}

// round 16
// speedup vs baseline: 1.3336x; 1.0571x over previous
#include <cuda_runtime.h>
#include <cuda_fp16.h>
#include <cstdint>

#define DIMD  1024
#define NH    16
#define DH    64
#define BATCH 4
#define SEQ   2048
#define MTOT  (BATCH*SEQ)   // 8192

// All k-pair word arrays use within-group-of-8 permutation:
//   pi(j) = 2*(j&3) + (j>>2)   (logical j, j+4 -> adjacent physical 2j', 2j'+1)
// Scratch (allocation-free rule: __device__ globals)
__device__ __align__(16) __half g_QH[BATCH*NH*SEQ*DH];   // [B,H,S,Dh] pre-scaled, pi-permuted
__device__ __align__(16) __half g_KH[BATCH*NH*SEQ*DH];   // pi-permuted
__device__ __align__(16) uint32_t g_VTP[BATCH*NH*DH*(SEQ/2)]; // V^T key-pairs, pi-permuted
__device__ __align__(16) __half g_AH[MTOT*DIMD];         // attn out, pi-permuted
__device__ __align__(16) __half g_XH[MTOT*DIMD];         // x fp16, pi-permuted
__device__ __align__(16) uint32_t g_WQP[64*3*DIMD*8];    // w_qkv [G=64][n=3072][w=8]
__device__ __align__(16) uint32_t g_WPP[64*DIMD*8];      // w_proj [G=64][n=1024][w=8]

__device__ __forceinline__ unsigned h2u(__half2 h) {
    return *reinterpret_cast<unsigned*>(&h);
}

__device__ __forceinline__ void mma_f16(
    float& c0, float& c1, float& c2, float& c3,
    unsigned a0, unsigned a1, unsigned a2, unsigned a3,
    unsigned b0, unsigned b1)
{
    asm volatile(
        "mma.sync.aligned.m16n8k16.row.col.f32.f16.f16.f32 "
        "{%0,%1,%2,%3}, {%4,%5,%6,%7}, {%8,%9}, {%0,%1,%2,%3};"
        : "+f"(c0), "+f"(c1), "+f"(c2), "+f"(c3)
        : "r"(a0), "r"(a1), "r"(a2), "r"(a3), "r"(b0), "r"(b1));
}

__device__ __forceinline__ void cpa16(void* dst, const void* src) {
    unsigned s = (unsigned)__cvta_generic_to_shared(dst);
    asm volatile("cp.async.cg.shared.global [%0], [%1], 16;" :: "r"(s), "l"(src));
}
__device__ __forceinline__ void cpa_commit() {
    asm volatile("cp.async.commit_group;");
}
template<int N>
__device__ __forceinline__ void cpa_wait() {
    asm volatile("cp.async.wait_group %0;" :: "n"(N));
}

// ---------------------------------------------------------------------------
// Prep: x -> fp16 pi-permuted rows; weights -> [G][n][8] pi-permuted words
// ---------------------------------------------------------------------------
#define NX2 (MTOT*256)               // uint2 units: 8192 rows * 256

__global__ __launch_bounds__(256)
void prep(const float* __restrict__ x, const float* __restrict__ wq,
          const float* __restrict__ wp)
{
    const int stride = gridDim.x * blockDim.x;
    // x: uint2 i -> (row, G, t): words (2t,2t+1) = logical (t, t+4) of group G
    for (int i = blockIdx.x*blockDim.x + threadIdx.x; i < NX2; i += stride) {
        const int row = i >> 8, r = i & 255;
        const int G = r >> 2, t = r & 3;
        const float* p = x + (long)row*1024 + G*16 + 2*t;
        float2 a = *(const float2*)(p);
        float2 b = *(const float2*)(p + 8);
        uint2 o;
        o.x = h2u(__floats2half2_rn(a.x, a.y));
        o.y = h2u(__floats2half2_rn(b.x, b.y));
        ((uint2*)g_XH)[i] = o;
    }
    // weights: word idx -> (G, n, w); j = (w&1)*4 + (w>>1); k2 = G*8+j
    const int NWQW = 64*3072*8;
    for (int idx = blockIdx.x*blockDim.x + threadIdx.x; idx < NWQW; idx += stride) {
        const int G = idx / (3072*8);
        const int rem = idx - G*(3072*8);
        const int n = rem >> 3, w = rem & 7;
        const int k2 = G*8 + (w&1)*4 + (w>>1);
        g_WQP[idx] = h2u(__floats2half2_rn(wq[(long)(2*k2)*3072 + n],
                                           wq[(long)(2*k2+1)*3072 + n]));
    }
    const int NWPW = 64*1024*8;
    for (int idx = blockIdx.x*blockDim.x + threadIdx.x; idx < NWPW; idx += stride) {
        const int G = idx >> 13;
        const int rem = idx & 8191;
        const int n = rem >> 3, w = rem & 7;
        const int k2 = G*8 + (w&1)*4 + (w>>1);
        g_WPP[idx] = h2u(__floats2half2_rn(wp[(long)(2*k2)*1024 + n],
                                           wp[(long)(2*k2+1)*1024 + n]));
    }
}

// ---------------------------------------------------------------------------
// FP16 GEMM: 3-stage cp.async, BK=64 halves, block 128x128, 8 warps (4Mx2N),
// warp 32x64. Fragment loads are LDS.64 (pi-paired). B n-major [g][n][8].
// MODE 0: A=g_XH, B=g_WQP (N=3072) -> Q(pre-scaled)/K fp16, V^T packed
// MODE 1: A=g_AH, B=g_WPP (N=1024) -> out fp32
// ---------------------------------------------------------------------------
#define GA_ST 40                  // 32 data words + 8 pad (stride % 32 == 8)
#define GA_STAGE (128*GA_ST)      // 5120 words
#define GB_STAGE (4*128*8)        // 4096 words: [g=4][n=128][w=8]
#define STG 3
#define GEMM_SMEM_WORDS (STG*(GA_STAGE+GB_STAGE))   // 27648
#define GEMM_SMEM_BYTES (GEMM_SMEM_WORDS*4)         // 110592

template<int MODE>
__global__ __launch_bounds__(256, 2)
void gemm_f16(const float* __restrict__ bias, float* __restrict__ out, int N)
{
    extern __shared__ uint32_t smw[];
    uint32_t* As2 = smw;                    // [STG][128][40]
    uint32_t* Bs2 = smw + STG*GA_STAGE;     // [STG][4][128][8]

    const int tid  = threadIdx.x;
    const int lane = tid & 31;
    const int warp = tid >> 5;
    const int warp_m = warp & 3;
    const int warp_n = warp >> 2;
    const int qr = lane >> 2;
    const int qc = lane & 3;

    const int rowStart = blockIdx.y * 128;
    const int colStart = blockIdx.x * 128;
    const __half* Ap = (MODE == 0) ? g_XH : g_AH;
    const uint32_t* Bp = (MODE == 0) ? g_WQP : g_WPP;

    float acc[2][8][4];
    #pragma unroll
    for (int i = 0; i < 2; i++)
        #pragma unroll
        for (int j = 0; j < 8; j++)
            #pragma unroll
            for (int c = 0; c < 4; c++) acc[i][j][c] = 0.f;

    auto load_stage = [&](int s, int k0) {   // k0 in halves, multiple of 64
        uint32_t* as = As2 + s*GA_STAGE;
        uint32_t* bs = Bs2 + s*GB_STAGE;
        const int G0 = k0 >> 4;              // global group base
        #pragma unroll
        for (int i = 0; i < 4; i++) {
            const int q = tid + i*256;       // A: 128 rows x 8 chunks
            cpa16(as + (q>>3)*GA_ST + ((q&7)<<2),
                  Ap + (long)(rowStart + (q>>3))*DIMD + k0 + ((q&7)<<3));
        }
        #pragma unroll
        for (int i = 0; i < 4; i++) {
            const int q = tid + i*256;       // B: (g, n, c) chunks
            const int g = q >> 8, n = (q >> 1) & 127, c = q & 1;
            cpa16(bs + g*1024 + n*8 + c*4,
                  Bp + (long)(G0 + g)*(N*8) + (long)(colStart + n)*8 + c*4);
        }
    };

    #pragma unroll
    for (int s = 0; s < STG-1; s++) { load_stage(s, s*64); cpa_commit(); }

    const int NITER = DIMD / 64;   // 16
    int cur = 0;
    for (int it = 0; it < NITER; it++) {
        cpa_wait<STG-2>();
        __syncthreads();

        const uint32_t* as = As2 + cur*GA_STAGE;
        const uint32_t* bs = Bs2 + cur*GB_STAGE;
        #pragma unroll
        for (int ks = 0; ks < 4; ks++) {
            unsigned a[2][4], b[8][2];
            #pragma unroll
            for (int ma = 0; ma < 2; ma++) {
                const int r = warp_m*32 + ma*16 + qr;
                uint2 u0 = *(const uint2*)(as + (r    )*GA_ST + ks*8 + 2*qc);
                uint2 u1 = *(const uint2*)(as + (r + 8)*GA_ST + ks*8 + 2*qc);
                a[ma][0] = u0.x; a[ma][1] = u1.x;
                a[ma][2] = u0.y; a[ma][3] = u1.y;
            }
            #pragma unroll
            for (int nb = 0; nb < 8; nb++) {
                uint2 ub = *(const uint2*)(bs + ks*1024 +
                                           (warp_n*64 + nb*8 + qr)*8 + 2*qc);
                b[nb][0] = ub.x; b[nb][1] = ub.y;
            }
            #pragma unroll
            for (int ma = 0; ma < 2; ma++)
                #pragma unroll
                for (int nb = 0; nb < 8; nb++)
                    mma_f16(acc[ma][nb][0], acc[ma][nb][1],
                            acc[ma][nb][2], acc[ma][nb][3],
                            a[ma][0], a[ma][1], a[ma][2], a[ma][3],
                            b[nb][0], b[nb][1]);
        }

        const int nk = it + STG - 1;
        if (nk < NITER) load_stage(nk % STG, nk*64);
        cpa_commit();
        cur = (cur + 1 == STG) ? 0 : cur + 1;
    }

    #pragma unroll
    for (int ma = 0; ma < 2; ma++) {
        const int row0 = rowStart + warp_m*32 + ma*16 + qr;
        #pragma unroll
        for (int nb = 0; nb < 8; nb++) {
            const int col = colStart + warp_n*64 + nb*8 + qc*2;
            const float b0 = bias[col], b1 = bias[col + 1];
            float v00 = acc[ma][nb][0] + b0, v01 = acc[ma][nb][1] + b1;
            float v10 = acc[ma][nb][2] + b0, v11 = acc[ma][nb][3] + b1;
            if (MODE == 0) {
                const int part = col >> 10;    // uniform per block
                const int dcol = col & 1023;
                const int head = dcol >> 6;
                const int dh   = dcol & 63;
                if (part == 2) {
                    // V^T key-pair words, pi-permuted: (sc, sc+4) -> one uint2
                    const float p00 = __shfl_down_sync(0xffffffffu, v00, 4);
                    const float p01 = __shfl_down_sync(0xffffffffu, v01, 4);
                    const float p10 = __shfl_down_sync(0xffffffffu, v10, 4);
                    const float p11 = __shfl_down_sync(0xffffffffu, v11, 4);
                    if (!(qr & 1)) {
                        const int bb = row0 >> 11, s = row0 & 2047;
                        const int sc = s >> 1;
                        const int off = (sc & ~7) + 2*(sc & 7);   // sc&7 in 0..3
                        const long rowoff =
                            (long)((bb*NH + head)*DH + dh)*(SEQ/2);
                        *(uint2*)(g_VTP + rowoff + off) =
                            make_uint2(h2u(__floats2half2_rn(v00, p00)),
                                       h2u(__floats2half2_rn(v10, p10)));
                        *(uint2*)(g_VTP + rowoff + SEQ/2 + off) =
                            make_uint2(h2u(__floats2half2_rn(v01, p01)),
                                       h2u(__floats2half2_rn(v11, p11)));
                    }
                } else {
                    if (part == 0) {   // fold 1/sqrt(Dh) into Q
                        v00 *= 0.125f; v01 *= 0.125f;
                        v10 *= 0.125f; v11 *= 0.125f;
                    }
                    // pi-permuted in-row half offset
                    const int php = (dh & ~15) | (4*qc + 2*(nb & 1));
                    __half* dst = (part == 0) ? g_QH : g_KH;
                    {
                        const int bb = row0 >> 11, s = row0 & 2047;
                        *(__half2*)(dst + (((bb*NH + head)*SEQ + s) << 6) + php) =
                            __floats2half2_rn(v00, v01);
                    }
                    {
                        const int row1 = row0 + 8;
                        const int bb = row1 >> 11, s = row1 & 2047;
                        *(__half2*)(dst + (((bb*NH + head)*SEQ + s) << 6) + php) =
                            __floats2half2_rn(v10, v11);
                    }
                }
            } else {
                *(float2*)(out + (long)row0*N + col) = make_float2(v00, v01);
                *(float2*)(out + (long)(row0 + 8)*N + col) = make_float2(v10, v11);
            }
        }
    }
}

// ---------------------------------------------------------------------------
// FP16 flash attention v5: all inputs pi-permuted -> fragment LDS.64.
// Q/K/V via cp.async, Q fragments hoisted, double-buffered K/V, one barrier.
// ---------------------------------------------------------------------------
#define AQ_ST 40
#define KV_STAGE (64*AQ_ST)                       // 2560 words
#define ATTN_SMEM_WORDS (128*AQ_ST + 4*KV_STAGE)  // 15360
#define ATTN_SMEM_BYTES (ATTN_SMEM_WORDS*4)       // 61440

__global__ __launch_bounds__(256, 2)
void attn_f16()
{
    extern __shared__ uint32_t smw[];
    uint32_t* Qs2 = smw;                         // [128][40]
    uint32_t* KsB = smw + 128*AQ_ST;             // [2][64][40]
    uint32_t* VtB = smw + 128*AQ_ST + 2*KV_STAGE;// [2][64][40]

    const int tid  = threadIdx.x;
    const int lane = tid & 31;
    const int warp = tid >> 5;
    const int qr = lane >> 2;
    const int qc = lane & 3;

    const int qt = (int)(gridDim.x - 1) - (int)blockIdx.x;   // heavy tiles first
    const int h = blockIdx.y, b = blockIdx.z;
    const int q0 = qt << 7;

    const long hb = (long)(b*NH + h) * SEQ * DH;
    const __half* Qg = g_QH + hb;
    const __half* Kg = g_KH + hb;
    const uint32_t* Vp = g_VTP + (long)(b*NH + h) * DH * (SEQ/2);

    // prologue: Q + K0 + V0, all cp.async (verbatim; data pre-permuted)
    #pragma unroll
    for (int i = 0; i < 4; i++) {
        const int q = tid + i*256;
        cpa16(Qs2 + (q>>3)*AQ_ST + ((q&7)<<2),
              Qg + (q0 + (q>>3))*DH + ((q&7)<<3));
    }
    #pragma unroll
    for (int i = 0; i < 2; i++) {
        const int q = tid + i*256;
        cpa16(KsB + (q>>3)*AQ_ST + ((q&7)<<2),
              Kg + (q>>3)*DH + ((q&7)<<3));
        cpa16(VtB + (q>>3)*AQ_ST + ((q&7)<<2),
              Vp + (q>>3)*(SEQ/2) + ((q&7)<<2));
    }
    cpa_commit();
    cpa_wait<0>();
    __syncthreads();

    // hoist Q fragments (LDS.64 pairs)
    const int rowA = warp*16 + qr;
    unsigned qa[4][4];
    #pragma unroll
    for (int ks = 0; ks < 4; ks++) {
        uint2 u0 = *(const uint2*)(Qs2 + (rowA    )*AQ_ST + ks*8 + 2*qc);
        uint2 u1 = *(const uint2*)(Qs2 + (rowA + 8)*AQ_ST + ks*8 + 2*qc);
        qa[ks][0] = u0.x; qa[ks][1] = u1.x;
        qa[ks][2] = u0.y; qa[ks][3] = u1.y;
    }

    float m0 = -1e30f, m1 = -1e30f, l0 = 0.f, l1 = 0.f;
    float o[8][4];
    #pragma unroll
    for (int nb = 0; nb < 8; nb++)
        #pragma unroll
        for (int c = 0; c < 4; c++) o[nb][c] = 0.f;

    const int ktiles = 2*qt + 2;

    for (int kt = 0; kt < ktiles; kt++) {
        const int cur = kt & 1;
        const bool more = (kt + 1) < ktiles;
        const uint32_t* Ks = KsB + cur*KV_STAGE;
        const uint32_t* Vt = VtB + cur*KV_STAGE;

        if (more) {
            const int k1 = (kt + 1) << 6;
            const int nxt = cur ^ 1;
            uint32_t* KsD = KsB + nxt*KV_STAGE;
            uint32_t* VtD = VtB + nxt*KV_STAGE;
            #pragma unroll
            for (int i = 0; i < 2; i++) {
                const int q = tid + i*256;
                cpa16(KsD + (q>>3)*AQ_ST + ((q&7)<<2),
                      Kg + (k1 + (q>>3))*DH + ((q&7)<<3));
                cpa16(VtD + (q>>3)*AQ_ST + ((q&7)<<2),
                      Vp + (q>>3)*(SEQ/2) + (k1>>1) + ((q&7)<<2));
            }
        }
        cpa_commit();

        // S = Q K^T
        float sv[8][4];
        #pragma unroll
        for (int nb = 0; nb < 8; nb++)
            #pragma unroll
            for (int c = 0; c < 4; c++) sv[nb][c] = 0.f;

        #pragma unroll
        for (int ks = 0; ks < 4; ks++) {
            #pragma unroll
            for (int nb = 0; nb < 8; nb++) {
                uint2 ub = *(const uint2*)(Ks + (nb*8+qr)*AQ_ST + ks*8 + 2*qc);
                mma_f16(sv[nb][0], sv[nb][1], sv[nb][2], sv[nb][3],
                        qa[ks][0], qa[ks][1], qa[ks][2], qa[ks][3],
                        ub.x, ub.y);
            }
        }

        if (kt >= 2*qt) {
            const int k0 = kt << 6;
            const int qg0 = q0 + rowA;
            #pragma unroll
            for (int nb = 0; nb < 8; nb++) {
                const int kg = k0 + nb*8 + 2*qc;
                if (kg     > qg0    ) sv[nb][0] = -1e30f;
                if (kg + 1 > qg0    ) sv[nb][1] = -1e30f;
                if (kg     > qg0 + 8) sv[nb][2] = -1e30f;
                if (kg + 1 > qg0 + 8) sv[nb][3] = -1e30f;
            }
        }

        float mx0 = -1e30f, mx1 = -1e30f;
        #pragma unroll
        for (int nb = 0; nb < 8; nb++) {
            mx0 = fmaxf(mx0, fmaxf(sv[nb][0], sv[nb][1]));
            mx1 = fmaxf(mx1, fmaxf(sv[nb][2], sv[nb][3]));
        }
        mx0 = fmaxf(mx0, __shfl_xor_sync(0xffffffffu, mx0, 1));
        mx0 = fmaxf(mx0, __shfl_xor_sync(0xffffffffu, mx0, 2));
        mx1 = fmaxf(mx1, __shfl_xor_sync(0xffffffffu, mx1, 1));
        mx1 = fmaxf(mx1, __shfl_xor_sync(0xffffffffu, mx1, 2));

        const float m0n = fmaxf(m0, mx0);
        const float m1n = fmaxf(m1, mx1);
        const float al0 = __expf(m0 - m0n);
        const float al1 = __expf(m1 - m1n);
        m0 = m0n; m1 = m1n;

        float ps0 = 0.f, ps1 = 0.f;
        #pragma unroll
        for (int nb = 0; nb < 8; nb++) {
            sv[nb][0] = __expf(sv[nb][0] - m0n);
            sv[nb][1] = __expf(sv[nb][1] - m0n);
            sv[nb][2] = __expf(sv[nb][2] - m1n);
            sv[nb][3] = __expf(sv[nb][3] - m1n);
            ps0 += sv[nb][0] + sv[nb][1];
            ps1 += sv[nb][2] + sv[nb][3];
        }
        ps0 += __shfl_xor_sync(0xffffffffu, ps0, 1);
        ps0 += __shfl_xor_sync(0xffffffffu, ps0, 2);
        ps1 += __shfl_xor_sync(0xffffffffu, ps1, 1);
        ps1 += __shfl_xor_sync(0xffffffffu, ps1, 2);
        l0 = l0*al0 + ps0;
        l1 = l1*al1 + ps1;
        #pragma unroll
        for (int nb = 0; nb < 8; nb++) {
            o[nb][0] *= al0; o[nb][1] *= al0;
            o[nb][2] *= al1; o[nb][3] *= al1;
        }

        // O += P @ V : P local, V fragments LDS.64
        #pragma unroll
        for (int ks = 0; ks < 4; ks++) {
            const unsigned a0 = h2u(__floats2half2_rn(sv[2*ks  ][0], sv[2*ks  ][1]));
            const unsigned a1 = h2u(__floats2half2_rn(sv[2*ks  ][2], sv[2*ks  ][3]));
            const unsigned a2 = h2u(__floats2half2_rn(sv[2*ks+1][0], sv[2*ks+1][1]));
            const unsigned a3 = h2u(__floats2half2_rn(sv[2*ks+1][2], sv[2*ks+1][3]));
            #pragma unroll
            for (int nb = 0; nb < 8; nb++) {
                uint2 uv = *(const uint2*)(Vt + (nb*8+qr)*AQ_ST + ks*8 + 2*qc);
                mma_f16(o[nb][0], o[nb][1], o[nb][2], o[nb][3],
                        a0, a1, a2, a3, uv.x, uv.y);
            }
        }

        if (more) {
            cpa_wait<0>();
            __syncthreads();
        }
    }

    // normalize + write merged-head [B,S,D] pi-permuted (feeds gemm<1>)
    const float inv0 = 1.0f / l0;
    const float inv1 = 1.0f / l1;
    const long r0 = (long)(b*SEQ + q0 + rowA);
    #pragma unroll
    for (int nb = 0; nb < 8; nb++) {
        const int colbase = h*DH + nb*8 + 2*qc;
        const int php = (colbase & ~15) | (4*qc + 2*(nb & 1));
        *(__half2*)(g_AH + r0*DIMD + php) =
            __floats2half2_rn(o[nb][0]*inv0, o[nb][1]*inv0);
        *(__half2*)(g_AH + (r0 + 8)*DIMD + php) =
            __floats2half2_rn(o[nb][2]*inv1, o[nb][3]*inv1);
    }
}

// ---------------------------------------------------------------------------
extern "C" void kernel_launch(void* const* d_in, const int* in_sizes, int n_in,
                              void* d_out, int out_size)
{
    const float* x      = (const float*)d_in[0];
    const float* w_qkv  = (const float*)d_in[1];
    const float* b_qkv  = (const float*)d_in[2];
    const float* w_proj = (const float*)d_in[3];
    const float* b_proj = (const float*)d_in[4];
    float* out = (float*)d_out;

    cudaFuncSetAttribute(gemm_f16<0>,
        cudaFuncAttributeMaxDynamicSharedMemorySize, GEMM_SMEM_BYTES);
    cudaFuncSetAttribute(gemm_f16<1>,
        cudaFuncAttributeMaxDynamicSharedMemorySize, GEMM_SMEM_BYTES);
    cudaFuncSetAttribute(attn_f16,
        cudaFuncAttributeMaxDynamicSharedMemorySize, ATTN_SMEM_BYTES);

    prep<<<1024, 256>>>(x, w_qkv, w_proj);
    gemm_f16<0><<<dim3(3*DIMD/128, MTOT/128), 256, GEMM_SMEM_BYTES>>>(b_qkv, nullptr, 3*DIMD);
    attn_f16<<<dim3(SEQ/128, NH, BATCH), 256, ATTN_SMEM_BYTES>>>();
    gemm_f16<1><<<dim3(DIMD/128, MTOT/128), 256, GEMM_SMEM_BYTES>>>(b_proj, out, DIMD);
}

// round 17
// speedup vs baseline: 1.3504x; 1.0125x over previous
#include <cuda_runtime.h>
#include <cuda_fp16.h>
#include <cstdint>

#define DIMD  1024
#define NH    16
#define DH    64
#define BATCH 4
#define SEQ   2048
#define MTOT  (BATCH*SEQ)   // 8192

// All k-pair word arrays use within-group-of-8 permutation:
//   pi(j) = 2*(j&3) + (j>>2)   (logical j, j+4 -> adjacent physical 2j', 2j'+1)
// Scratch (allocation-free rule: __device__ globals)
__device__ __align__(16) __half g_QH[BATCH*NH*SEQ*DH];   // [B,H,S,Dh] pre-scaled, pi-permuted
__device__ __align__(16) __half g_KH[BATCH*NH*SEQ*DH];   // pi-permuted
__device__ __align__(16) uint32_t g_VTP[BATCH*NH*DH*(SEQ/2)]; // V^T key-pairs, pi-permuted
__device__ __align__(16) __half g_AH[MTOT*DIMD];         // attn out, pi-permuted
__device__ __align__(16) __half g_XH[MTOT*DIMD];         // x fp16, pi-permuted
__device__ __align__(16) uint32_t g_WQP[64*3*DIMD*8];    // w_qkv [G=64][n=3072][w=8]
__device__ __align__(16) uint32_t g_WPP[64*DIMD*8];      // w_proj [G=64][n=1024][w=8]

__device__ __forceinline__ unsigned h2u(__half2 h) {
    return *reinterpret_cast<unsigned*>(&h);
}

__device__ __forceinline__ void mma_f16(
    float& c0, float& c1, float& c2, float& c3,
    unsigned a0, unsigned a1, unsigned a2, unsigned a3,
    unsigned b0, unsigned b1)
{
    asm volatile(
        "mma.sync.aligned.m16n8k16.row.col.f32.f16.f16.f32 "
        "{%0,%1,%2,%3}, {%4,%5,%6,%7}, {%8,%9}, {%0,%1,%2,%3};"
        : "+f"(c0), "+f"(c1), "+f"(c2), "+f"(c3)
        : "r"(a0), "r"(a1), "r"(a2), "r"(a3), "r"(b0), "r"(b1));
}

__device__ __forceinline__ void cpa16(void* dst, const void* src) {
    unsigned s = (unsigned)__cvta_generic_to_shared(dst);
    asm volatile("cp.async.cg.shared.global [%0], [%1], 16;" :: "r"(s), "l"(src));
}
__device__ __forceinline__ void cpa_commit() {
    asm volatile("cp.async.commit_group;");
}
template<int N>
__device__ __forceinline__ void cpa_wait() {
    asm volatile("cp.async.wait_group %0;" :: "n"(N));
}

// ---------------------------------------------------------------------------
// Prep: x -> fp16 pi-permuted rows; weights -> [G][n][8] pi-permuted words.
// Weight loop: thread = (G, n) -> reads coalesced across the warp (same
// k-row, consecutive n) and writes 8 contiguous words (2x uint4).
// ---------------------------------------------------------------------------
#define NX2 (MTOT*256)               // uint2 units: 8192 rows * 256

__global__ __launch_bounds__(256)
void prep(const float* __restrict__ x, const float* __restrict__ wq,
          const float* __restrict__ wp)
{
    const int stride = gridDim.x * blockDim.x;
    // x: uint2 i -> (row, G, t): words (2t,2t+1) = logical (t, t+4) of group G
    for (int i = blockIdx.x*blockDim.x + threadIdx.x; i < NX2; i += stride) {
        const int row = i >> 8, r = i & 255;
        const int G = r >> 2, t = r & 3;
        const float* p = x + (long)row*1024 + G*16 + 2*t;
        float2 a = *(const float2*)(p);
        float2 b = *(const float2*)(p + 8);
        uint2 o;
        o.x = h2u(__floats2half2_rn(a.x, a.y));
        o.y = h2u(__floats2half2_rn(b.x, b.y));
        ((uint2*)g_XH)[i] = o;
    }
    // w_qkv: thread = (G, n); 16 coalesced reads, 2 uint4 writes
    const int NWQT = 64*3072;
    for (int idx = blockIdx.x*blockDim.x + threadIdx.x; idx < NWQT; idx += stride) {
        const int G = idx / 3072, n = idx - G*3072;
        uint32_t o[8];
        #pragma unroll
        for (int w = 0; w < 8; w++) {
            const int k2 = G*8 + (w & 1)*4 + (w >> 1);
            o[w] = h2u(__floats2half2_rn(wq[(long)(2*k2)*3072 + n],
                                         wq[(long)(2*k2 + 1)*3072 + n]));
        }
        uint4* dst = (uint4*)(g_WQP + (long)idx*8);
        dst[0] = make_uint4(o[0], o[1], o[2], o[3]);
        dst[1] = make_uint4(o[4], o[5], o[6], o[7]);
    }
    // w_proj: same scheme
    const int NWPT = 64*1024;
    for (int idx = blockIdx.x*blockDim.x + threadIdx.x; idx < NWPT; idx += stride) {
        const int G = idx >> 10, n = idx & 1023;
        uint32_t o[8];
        #pragma unroll
        for (int w = 0; w < 8; w++) {
            const int k2 = G*8 + (w & 1)*4 + (w >> 1);
            o[w] = h2u(__floats2half2_rn(wp[(long)(2*k2)*1024 + n],
                                         wp[(long)(2*k2 + 1)*1024 + n]));
        }
        uint4* dst = (uint4*)(g_WPP + (long)idx*8);
        dst[0] = make_uint4(o[0], o[1], o[2], o[3]);
        dst[1] = make_uint4(o[4], o[5], o[6], o[7]);
    }
}

// ---------------------------------------------------------------------------
// FP16 GEMM: 3-stage cp.async, BK=64 halves, block 128x128, 8 warps (4Mx2N),
// warp 32x64. Fragment loads are LDS.64 (pi-paired). B n-major [g][n][8].
// MODE 0: A=g_XH, B=g_WQP (N=3072) -> Q(pre-scaled)/K fp16, V^T packed
// MODE 1: A=g_AH, B=g_WPP (N=1024) -> out fp32
// ---------------------------------------------------------------------------
#define GA_ST 40                  // 32 data words + 8 pad (stride % 32 == 8)
#define GA_STAGE (128*GA_ST)      // 5120 words
#define GB_STAGE (4*128*8)        // 4096 words: [g=4][n=128][w=8]
#define STG 3
#define GEMM_SMEM_WORDS (STG*(GA_STAGE+GB_STAGE))   // 27648
#define GEMM_SMEM_BYTES (GEMM_SMEM_WORDS*4)         // 110592

template<int MODE>
__global__ __launch_bounds__(256, 2)
void gemm_f16(const float* __restrict__ bias, float* __restrict__ out, int N)
{
    extern __shared__ uint32_t smw[];
    uint32_t* As2 = smw;                    // [STG][128][40]
    uint32_t* Bs2 = smw + STG*GA_STAGE;     // [STG][4][128][8]

    const int tid  = threadIdx.x;
    const int lane = tid & 31;
    const int warp = tid >> 5;
    const int warp_m = warp & 3;
    const int warp_n = warp >> 2;
    const int qr = lane >> 2;
    const int qc = lane & 3;

    const int rowStart = blockIdx.y * 128;
    const int colStart = blockIdx.x * 128;
    const __half* Ap = (MODE == 0) ? g_XH : g_AH;
    const uint32_t* Bp = (MODE == 0) ? g_WQP : g_WPP;

    float acc[2][8][4];
    #pragma unroll
    for (int i = 0; i < 2; i++)
        #pragma unroll
        for (int j = 0; j < 8; j++)
            #pragma unroll
            for (int c = 0; c < 4; c++) acc[i][j][c] = 0.f;

    auto load_stage = [&](int s, int k0) {   // k0 in halves, multiple of 64
        uint32_t* as = As2 + s*GA_STAGE;
        uint32_t* bs = Bs2 + s*GB_STAGE;
        const int G0 = k0 >> 4;              // global group base
        #pragma unroll
        for (int i = 0; i < 4; i++) {
            const int q = tid + i*256;       // A: 128 rows x 8 chunks
            cpa16(as + (q>>3)*GA_ST + ((q&7)<<2),
                  Ap + (long)(rowStart + (q>>3))*DIMD + k0 + ((q&7)<<3));
        }
        #pragma unroll
        for (int i = 0; i < 4; i++) {
            const int q = tid + i*256;       // B: (g, n, c) chunks
            const int g = q >> 8, n = (q >> 1) & 127, c = q & 1;
            cpa16(bs + g*1024 + n*8 + c*4,
                  Bp + (long)(G0 + g)*(N*8) + (long)(colStart + n)*8 + c*4);
        }
    };

    #pragma unroll
    for (int s = 0; s < STG-1; s++) { load_stage(s, s*64); cpa_commit(); }

    const int NITER = DIMD / 64;   // 16
    int cur = 0;
    for (int it = 0; it < NITER; it++) {
        cpa_wait<STG-2>();
        __syncthreads();

        const uint32_t* as = As2 + cur*GA_STAGE;
        const uint32_t* bs = Bs2 + cur*GB_STAGE;
        #pragma unroll
        for (int ks = 0; ks < 4; ks++) {
            unsigned a[2][4], b[8][2];
            #pragma unroll
            for (int ma = 0; ma < 2; ma++) {
                const int r = warp_m*32 + ma*16 + qr;
                uint2 u0 = *(const uint2*)(as + (r    )*GA_ST + ks*8 + 2*qc);
                uint2 u1 = *(const uint2*)(as + (r + 8)*GA_ST + ks*8 + 2*qc);
                a[ma][0] = u0.x; a[ma][1] = u1.x;
                a[ma][2] = u0.y; a[ma][3] = u1.y;
            }
            #pragma unroll
            for (int nb = 0; nb < 8; nb++) {
                uint2 ub = *(const uint2*)(bs + ks*1024 +
                                           (warp_n*64 + nb*8 + qr)*8 + 2*qc);
                b[nb][0] = ub.x; b[nb][1] = ub.y;
            }
            #pragma unroll
            for (int ma = 0; ma < 2; ma++)
                #pragma unroll
                for (int nb = 0; nb < 8; nb++)
                    mma_f16(acc[ma][nb][0], acc[ma][nb][1],
                            acc[ma][nb][2], acc[ma][nb][3],
                            a[ma][0], a[ma][1], a[ma][2], a[ma][3],
                            b[nb][0], b[nb][1]);
        }

        const int nk = it + STG - 1;
        if (nk < NITER) load_stage(nk % STG, nk*64);
        cpa_commit();
        cur = (cur + 1 == STG) ? 0 : cur + 1;
    }

    #pragma unroll
    for (int ma = 0; ma < 2; ma++) {
        const int row0 = rowStart + warp_m*32 + ma*16 + qr;
        #pragma unroll
        for (int nb = 0; nb < 8; nb++) {
            const int col = colStart + warp_n*64 + nb*8 + qc*2;
            const float b0 = bias[col], b1 = bias[col + 1];
            float v00 = acc[ma][nb][0] + b0, v01 = acc[ma][nb][1] + b1;
            float v10 = acc[ma][nb][2] + b0, v11 = acc[ma][nb][3] + b1;
            if (MODE == 0) {
                const int part = col >> 10;    // uniform per block
                const int dcol = col & 1023;
                const int head = dcol >> 6;
                const int dh   = dcol & 63;
                if (part == 2) {
                    // V^T key-pair words, pi-permuted: (sc, sc+4) -> one uint2
                    const float p00 = __shfl_down_sync(0xffffffffu, v00, 4);
                    const float p01 = __shfl_down_sync(0xffffffffu, v01, 4);
                    const float p10 = __shfl_down_sync(0xffffffffu, v10, 4);
                    const float p11 = __shfl_down_sync(0xffffffffu, v11, 4);
                    if (!(qr & 1)) {
                        const int bb = row0 >> 11, s = row0 & 2047;
                        const int sc = s >> 1;
                        const int off = (sc & ~7) + 2*(sc & 7);   // sc&7 in 0..3
                        const long rowoff =
                            (long)((bb*NH + head)*DH + dh)*(SEQ/2);
                        *(uint2*)(g_VTP + rowoff + off) =
                            make_uint2(h2u(__floats2half2_rn(v00, p00)),
                                       h2u(__floats2half2_rn(v10, p10)));
                        *(uint2*)(g_VTP + rowoff + SEQ/2 + off) =
                            make_uint2(h2u(__floats2half2_rn(v01, p01)),
                                       h2u(__floats2half2_rn(v11, p11)));
                    }
                } else {
                    if (part == 0) {   // fold 1/sqrt(Dh) into Q
                        v00 *= 0.125f; v01 *= 0.125f;
                        v10 *= 0.125f; v11 *= 0.125f;
                    }
                    // pi-permuted in-row half offset
                    const int php = (dh & ~15) | (4*qc + 2*(nb & 1));
                    __half* dst = (part == 0) ? g_QH : g_KH;
                    {
                        const int bb = row0 >> 11, s = row0 & 2047;
                        *(__half2*)(dst + (((bb*NH + head)*SEQ + s) << 6) + php) =
                            __floats2half2_rn(v00, v01);
                    }
                    {
                        const int row1 = row0 + 8;
                        const int bb = row1 >> 11, s = row1 & 2047;
                        *(__half2*)(dst + (((bb*NH + head)*SEQ + s) << 6) + php) =
                            __floats2half2_rn(v10, v11);
                    }
                }
            } else {
                *(float2*)(out + (long)row0*N + col) = make_float2(v00, v01);
                *(float2*)(out + (long)(row0 + 8)*N + col) = make_float2(v10, v11);
            }
        }
    }
}

// ---------------------------------------------------------------------------
// FP16 flash attention v5: all inputs pi-permuted -> fragment LDS.64.
// Q/K/V via cp.async, Q fragments hoisted, double-buffered K/V, one barrier.
// ---------------------------------------------------------------------------
#define AQ_ST 40
#define KV_STAGE (64*AQ_ST)                       // 2560 words
#define ATTN_SMEM_WORDS (128*AQ_ST + 4*KV_STAGE)  // 15360
#define ATTN_SMEM_BYTES (ATTN_SMEM_WORDS*4)       // 61440

__global__ __launch_bounds__(256, 2)
void attn_f16()
{
    extern __shared__ uint32_t smw[];
    uint32_t* Qs2 = smw;                         // [128][40]
    uint32_t* KsB = smw + 128*AQ_ST;             // [2][64][40]
    uint32_t* VtB = smw + 128*AQ_ST + 2*KV_STAGE;// [2][64][40]

    const int tid  = threadIdx.x;
    const int lane = tid & 31;
    const int warp = tid >> 5;
    const int qr = lane >> 2;
    const int qc = lane & 3;

    const int qt = (int)(gridDim.x - 1) - (int)blockIdx.x;   // heavy tiles first
    const int h = blockIdx.y, b = blockIdx.z;
    const int q0 = qt << 7;

    const long hb = (long)(b*NH + h) * SEQ * DH;
    const __half* Qg = g_QH + hb;
    const __half* Kg = g_KH + hb;
    const uint32_t* Vp = g_VTP + (long)(b*NH + h) * DH * (SEQ/2);

    // prologue: Q + K0 + V0, all cp.async (verbatim; data pre-permuted)
    #pragma unroll
    for (int i = 0; i < 4; i++) {
        const int q = tid + i*256;
        cpa16(Qs2 + (q>>3)*AQ_ST + ((q&7)<<2),
              Qg + (q0 + (q>>3))*DH + ((q&7)<<3));
    }
    #pragma unroll
    for (int i = 0; i < 2; i++) {
        const int q = tid + i*256;
        cpa16(KsB + (q>>3)*AQ_ST + ((q&7)<<2),
              Kg + (q>>3)*DH + ((q&7)<<3));
        cpa16(VtB + (q>>3)*AQ_ST + ((q&7)<<2),
              Vp + (q>>3)*(SEQ/2) + ((q&7)<<2));
    }
    cpa_commit();
    cpa_wait<0>();
    __syncthreads();

    // hoist Q fragments (LDS.64 pairs)
    const int rowA = warp*16 + qr;
    unsigned qa[4][4];
    #pragma unroll
    for (int ks = 0; ks < 4; ks++) {
        uint2 u0 = *(const uint2*)(Qs2 + (rowA    )*AQ_ST + ks*8 + 2*qc);
        uint2 u1 = *(const uint2*)(Qs2 + (rowA + 8)*AQ_ST + ks*8 + 2*qc);
        qa[ks][0] = u0.x; qa[ks][1] = u1.x;
        qa[ks][2] = u0.y; qa[ks][3] = u1.y;
    }

    float m0 = -1e30f, m1 = -1e30f, l0 = 0.f, l1 = 0.f;
    float o[8][4];
    #pragma unroll
    for (int nb = 0; nb < 8; nb++)
        #pragma unroll
        for (int c = 0; c < 4; c++) o[nb][c] = 0.f;

    const int ktiles = 2*qt + 2;

    for (int kt = 0; kt < ktiles; kt++) {
        const int cur = kt & 1;
        const bool more = (kt + 1) < ktiles;
        const uint32_t* Ks = KsB + cur*KV_STAGE;
        const uint32_t* Vt = VtB + cur*KV_STAGE;

        if (more) {
            const int k1 = (kt + 1) << 6;
            const int nxt = cur ^ 1;
            uint32_t* KsD = KsB + nxt*KV_STAGE;
            uint32_t* VtD = VtB + nxt*KV_STAGE;
            #pragma unroll
            for (int i = 0; i < 2; i++) {
                const int q = tid + i*256;
                cpa16(KsD + (q>>3)*AQ_ST + ((q&7)<<2),
                      Kg + (k1 + (q>>3))*DH + ((q&7)<<3));
                cpa16(VtD + (q>>3)*AQ_ST + ((q&7)<<2),
                      Vp + (q>>3)*(SEQ/2) + (k1>>1) + ((q&7)<<2));
            }
        }
        cpa_commit();

        // S = Q K^T
        float sv[8][4];
        #pragma unroll
        for (int nb = 0; nb < 8; nb++)
            #pragma unroll
            for (int c = 0; c < 4; c++) sv[nb][c] = 0.f;

        #pragma unroll
        for (int ks = 0; ks < 4; ks++) {
            #pragma unroll
            for (int nb = 0; nb < 8; nb++) {
                uint2 ub = *(const uint2*)(Ks + (nb*8+qr)*AQ_ST + ks*8 + 2*qc);
                mma_f16(sv[nb][0], sv[nb][1], sv[nb][2], sv[nb][3],
                        qa[ks][0], qa[ks][1], qa[ks][2], qa[ks][3],
                        ub.x, ub.y);
            }
        }

        if (kt >= 2*qt) {
            const int k0 = kt << 6;
            const int qg0 = q0 + rowA;
            #pragma unroll
            for (int nb = 0; nb < 8; nb++) {
                const int kg = k0 + nb*8 + 2*qc;
                if (kg     > qg0    ) sv[nb][0] = -1e30f;
                if (kg + 1 > qg0    ) sv[nb][1] = -1e30f;
                if (kg     > qg0 + 8) sv[nb][2] = -1e30f;
                if (kg + 1 > qg0 + 8) sv[nb][3] = -1e30f;
            }
        }

        float mx0 = -1e30f, mx1 = -1e30f;
        #pragma unroll
        for (int nb = 0; nb < 8; nb++) {
            mx0 = fmaxf(mx0, fmaxf(sv[nb][0], sv[nb][1]));
            mx1 = fmaxf(mx1, fmaxf(sv[nb][2], sv[nb][3]));
        }
        mx0 = fmaxf(mx0, __shfl_xor_sync(0xffffffffu, mx0, 1));
        mx0 = fmaxf(mx0, __shfl_xor_sync(0xffffffffu, mx0, 2));
        mx1 = fmaxf(mx1, __shfl_xor_sync(0xffffffffu, mx1, 1));
        mx1 = fmaxf(mx1, __shfl_xor_sync(0xffffffffu, mx1, 2));

        const float m0n = fmaxf(m0, mx0);
        const float m1n = fmaxf(m1, mx1);
        const float al0 = __expf(m0 - m0n);
        const float al1 = __expf(m1 - m1n);
        m0 = m0n; m1 = m1n;

        float ps0 = 0.f, ps1 = 0.f;
        #pragma unroll
        for (int nb = 0; nb < 8; nb++) {
            sv[nb][0] = __expf(sv[nb][0] - m0n);
            sv[nb][1] = __expf(sv[nb][1] - m0n);
            sv[nb][2] = __expf(sv[nb][2] - m1n);
            sv[nb][3] = __expf(sv[nb][3] - m1n);
            ps0 += sv[nb][0] + sv[nb][1];
            ps1 += sv[nb][2] + sv[nb][3];
        }
        ps0 += __shfl_xor_sync(0xffffffffu, ps0, 1);
        ps0 += __shfl_xor_sync(0xffffffffu, ps0, 2);
        ps1 += __shfl_xor_sync(0xffffffffu, ps1, 1);
        ps1 += __shfl_xor_sync(0xffffffffu, ps1, 2);
        l0 = l0*al0 + ps0;
        l1 = l1*al1 + ps1;
        #pragma unroll
        for (int nb = 0; nb < 8; nb++) {
            o[nb][0] *= al0; o[nb][1] *= al0;
            o[nb][2] *= al1; o[nb][3] *= al1;
        }

        // O += P @ V : P local, V fragments LDS.64
        #pragma unroll
        for (int ks = 0; ks < 4; ks++) {
            const unsigned a0 = h2u(__floats2half2_rn(sv[2*ks  ][0], sv[2*ks  ][1]));
            const unsigned a1 = h2u(__floats2half2_rn(sv[2*ks  ][2], sv[2*ks  ][3]));
            const unsigned a2 = h2u(__floats2half2_rn(sv[2*ks+1][0], sv[2*ks+1][1]));
            const unsigned a3 = h2u(__floats2half2_rn(sv[2*ks+1][2], sv[2*ks+1][3]));
            #pragma unroll
            for (int nb = 0; nb < 8; nb++) {
                uint2 uv = *(const uint2*)(Vt + (nb*8+qr)*AQ_ST + ks*8 + 2*qc);
                mma_f16(o[nb][0], o[nb][1], o[nb][2], o[nb][3],
                        a0, a1, a2, a3, uv.x, uv.y);
            }
        }

        if (more) {
            cpa_wait<0>();
            __syncthreads();
        }
    }

    // normalize + write merged-head [B,S,D] pi-permuted (feeds gemm<1>)
    const float inv0 = 1.0f / l0;
    const float inv1 = 1.0f / l1;
    const long r0 = (long)(b*SEQ + q0 + rowA);
    #pragma unroll
    for (int nb = 0; nb < 8; nb++) {
        const int colbase = h*DH + nb*8 + 2*qc;
        const int php = (colbase & ~15) | (4*qc + 2*(nb & 1));
        *(__half2*)(g_AH + r0*DIMD + php) =
            __floats2half2_rn(o[nb][0]*inv0, o[nb][1]*inv0);
        *(__half2*)(g_AH + (r0 + 8)*DIMD + php) =
            __floats2half2_rn(o[nb][2]*inv1, o[nb][3]*inv1);
    }
}

// ---------------------------------------------------------------------------
extern "C" void kernel_launch(void* const* d_in, const int* in_sizes, int n_in,
                              void* d_out, int out_size)
{
    const float* x      = (const float*)d_in[0];
    const float* w_qkv  = (const float*)d_in[1];
    const float* b_qkv  = (const float*)d_in[2];
    const float* w_proj = (const float*)d_in[3];
    const float* b_proj = (const float*)d_in[4];
    float* out = (float*)d_out;

    cudaFuncSetAttribute(gemm_f16<0>,
        cudaFuncAttributeMaxDynamicSharedMemorySize, GEMM_SMEM_BYTES);
    cudaFuncSetAttribute(gemm_f16<1>,
        cudaFuncAttributeMaxDynamicSharedMemorySize, GEMM_SMEM_BYTES);
    cudaFuncSetAttribute(attn_f16,
        cudaFuncAttributeMaxDynamicSharedMemorySize, ATTN_SMEM_BYTES);

    prep<<<1024, 256>>>(x, w_qkv, w_proj);
    gemm_f16<0><<<dim3(3*DIMD/128, MTOT/128), 256, GEMM_SMEM_BYTES>>>(b_qkv, nullptr, 3*DIMD);
    attn_f16<<<dim3(SEQ/128, NH, BATCH), 256, ATTN_SMEM_BYTES>>>();
    gemm_f16<1><<<dim3(DIMD/128, MTOT/128), 256, GEMM_SMEM_BYTES>>>(b_proj, out, DIMD);
}